// round 1
// baseline (speedup 1.0000x reference)
#include <cuda_runtime.h>
#include <math.h>

#define BATCH 16384
#define OUTC  523   // 7 + 4 + 512

// ---------------- scratch (static __device__, no allocation) ----------------
__device__ float g_buf1[BATCH * 1024];
__device__ float g_buf2[BATCH * 1024];
__device__ int   g_ridx[BATCH];
__device__ int   g_cnt[8];
__device__ int   g_off[8];
__device__ int   g_cur[8];

__device__ __forceinline__ float elu_f(float v) {
    return v > 0.f ? v : expm1f(v);
}
__device__ __forceinline__ float softplus_f(float v) {
    // stable: logaddexp(v, 0)
    return fmaxf(v, 0.f) + log1pf(expf(-fabsf(v)));
}

// ---------------- grouping kernels (bucket rows by t, K=7) ----------------
__global__ void k_init() {
    if (threadIdx.x < 8) g_cnt[threadIdx.x] = 0;
}
__global__ void k_hist(const int* __restrict__ t) {
    int i = blockIdx.x * blockDim.x + threadIdx.x;
    if (i < BATCH) atomicAdd(&g_cnt[t[i]], 1);
}
__global__ void k_off() {
    if (threadIdx.x == 0) {
        int s = 0;
        for (int i = 0; i < 7; i++) { g_off[i] = s; g_cur[i] = s; s += g_cnt[i]; }
    }
}
__global__ void k_scatter(const int* __restrict__ t) {
    int i = blockIdx.x * blockDim.x + threadIdx.x;
    if (i < BATCH) {
        int p = atomicAdd(&g_cur[t[i]], 1);
        g_ridx[p] = i;
    }
}

// ---------------- main SGEMM: C[M,N] = act(A[M,Kd] @ W[Kd,N] + bias [+ y*w0 + d*w1]) ----
// 128x128 tile, BK=8, 256 threads, 8x8 per thread. M=BATCH, N % 128 == 0, Kd % 8 == 0.
template <int ACT, bool ADD_YD>
__global__ void __launch_bounds__(256)
sgemm(const float* __restrict__ A, const float* __restrict__ W,
      const float* __restrict__ bias, float* __restrict__ C,
      int N, int Kd,
      const float* __restrict__ yv, const float* __restrict__ dv,
      const float* __restrict__ wyd)
{
    __shared__ float sA[8][128];
    __shared__ float sB[8][128];
    const int bm = blockIdx.y * 128, bn = blockIdx.x * 128;
    const int tid = threadIdx.x;
    const int tx = tid & 15, ty = tid >> 4;
    const int arow = tid >> 1, acol = (tid & 1) * 4;
    const int brow = tid >> 5, bcol = (tid & 31) * 4;

    float acc[8][8];
#pragma unroll
    for (int i = 0; i < 8; i++)
#pragma unroll
        for (int j = 0; j < 8; j++) acc[i][j] = 0.f;

    const float* Ap = A + (long)(bm + arow) * Kd + acol;
    const float* Wp = W + (long)brow * N + bn + bcol;

    for (int k0 = 0; k0 < Kd; k0 += 8) {
        float4 av = *(const float4*)(Ap + k0);
        float4 bv = *(const float4*)(Wp + (long)k0 * N);
        sA[acol + 0][arow] = av.x; sA[acol + 1][arow] = av.y;
        sA[acol + 2][arow] = av.z; sA[acol + 3][arow] = av.w;
        *(float4*)(&sB[brow][bcol]) = bv;
        __syncthreads();
#pragma unroll
        for (int k = 0; k < 8; k++) {
            float ar[8], br[8];
            *(float4*)(ar)     = *(const float4*)(&sA[k][ty * 8]);
            *(float4*)(ar + 4) = *(const float4*)(&sA[k][ty * 8 + 4]);
            *(float4*)(br)     = *(const float4*)(&sB[k][tx * 8]);
            *(float4*)(br + 4) = *(const float4*)(&sB[k][tx * 8 + 4]);
#pragma unroll
            for (int i = 0; i < 8; i++)
#pragma unroll
                for (int j = 0; j < 8; j++)
                    acc[i][j] = fmaf(ar[i], br[j], acc[i][j]);
        }
        __syncthreads();
    }

#pragma unroll
    for (int i = 0; i < 8; i++) {
        int m = bm + ty * 8 + i;
        float ya = 0.f, da = 0.f;
        if (ADD_YD) { ya = yv[m]; da = dv[m]; }
#pragma unroll
        for (int j = 0; j < 8; j++) {
            int n = bn + tx * 8 + j;
            float v = acc[i][j] + bias[n];
            if (ADD_YD) v += ya * wyd[n] + da * wyd[N + n];
            if (ACT == 1) v = elu_f(v);
            C[(long)m * N + n] = v;
        }
    }
}

// ---------------- t head: out[:,0:7] = clip(elu(ht @ tw2 + tb2), -10, 10) ----------------
// ht: [B,256], tw2: [256,7]. One warp per row.
__global__ void thead_kernel(const float* __restrict__ hid,
                             const float* __restrict__ tw2,
                             const float* __restrict__ tb2,
                             float* __restrict__ out)
{
    int w = (blockIdx.x * blockDim.x + threadIdx.x) >> 5;
    int lane = threadIdx.x & 31;
    if (w >= BATCH) return;
    const float* hr = hid + (long)w * 256;
    float acc[7] = {0.f, 0.f, 0.f, 0.f, 0.f, 0.f, 0.f};
    for (int k = lane; k < 256; k += 32) {
        float h = hr[k];
        const float* wr = tw2 + k * 7;
#pragma unroll
        for (int j = 0; j < 7; j++) acc[j] = fmaf(h, wr[j], acc[j]);
    }
#pragma unroll
    for (int j = 0; j < 7; j++)
        for (int o = 16; o > 0; o >>= 1) acc[j] += __shfl_xor_sync(0xffffffffu, acc[j], o);
    if (lane == 0) {
#pragma unroll
        for (int j = 0; j < 7; j++) {
            float v = elu_f(acc[j] + tb2[j]);
            out[(long)w * OUTC + j] = fminf(fmaxf(v, -10.f), 10.f);
        }
    }
}

// ---------------- y/d heads: normal head with per-row t gather ----------------
// hid: [B,1024], hW: [K,1024,2], hb: [K,2]. One warp per row.
__global__ void head2_kernel(const float* __restrict__ hid,
                             const int* __restrict__ t,
                             const float* __restrict__ hW,
                             const float* __restrict__ hb,
                             float* __restrict__ out, int col0)
{
    int w = (blockIdx.x * blockDim.x + threadIdx.x) >> 5;
    int lane = threadIdx.x & 31;
    if (w >= BATCH) return;
    int tt = t[w];
    const float*  hr = hid + (long)w * 1024;
    const float2* wp = (const float2*)(hW + (long)tt * 2048);
    float a0 = 0.f, a1 = 0.f;
    for (int k = lane; k < 1024; k += 32) {
        float h = hr[k];
        float2 ww = wp[k];
        a0 = fmaf(h, ww.x, a0);
        a1 = fmaf(h, ww.y, a1);
    }
    for (int o = 16; o > 0; o >>= 1) {
        a0 += __shfl_xor_sync(0xffffffffu, a0, o);
        a1 += __shfl_xor_sync(0xffffffffu, a1, o);
    }
    if (lane == 0) {
        float loc = fminf(fmaxf(a0 + hb[tt * 2 + 0], -1e6f), 1e6f);
        float sc  = fminf(softplus_f(a1 + hb[tt * 2 + 1]) + 1e-3f, 1e6f);
        out[(long)w * OUTC + col0]     = loc;
        out[(long)w * OUTC + col0 + 1] = sc;
    }
}

// ---------------- z head: grouped-by-t gathered GEMM ----------------
// hid: [B,1024], zhW: [7,1024,512], zhb: [7,512].
// grid: (512/128, ceil(B/128), 7). Blocks beyond bucket count exit early.
__global__ void __launch_bounds__(256)
zhead_kernel(const float* __restrict__ hid,
             const float* __restrict__ zhW,
             const float* __restrict__ zhb,
             float* __restrict__ out)
{
    const int tgrp = blockIdx.z;
    const int cnt = g_cnt[tgrp];
    const int m0 = blockIdx.y * 128;
    if (m0 >= cnt) return;
    const int base = g_off[tgrp];
    const int bn = blockIdx.x * 128;

    __shared__ float sA[8][128];
    __shared__ float sB[8][128];
    __shared__ int srow[128];

    const int tid = threadIdx.x;
    if (tid < 128) {
        int mi = m0 + tid;
        srow[tid] = (mi < cnt) ? g_ridx[base + mi] : -1;
    }
    __syncthreads();

    const int tx = tid & 15, ty = tid >> 4;
    const int arow = tid >> 1, acol = (tid & 1) * 4;
    const int brow = tid >> 5, bcol = (tid & 31) * 4;

    int ag = srow[arow]; if (ag < 0) ag = srow[0];
    const float* Ap = hid + (long)ag * 1024 + acol;
    const float* Wp = zhW + (long)tgrp * 1024 * 512 + (long)brow * 512 + bn + bcol;

    float acc[8][8];
#pragma unroll
    for (int i = 0; i < 8; i++)
#pragma unroll
        for (int j = 0; j < 8; j++) acc[i][j] = 0.f;

    for (int k0 = 0; k0 < 1024; k0 += 8) {
        float4 av = *(const float4*)(Ap + k0);
        float4 bv = *(const float4*)(Wp + (long)k0 * 512);
        sA[acol + 0][arow] = av.x; sA[acol + 1][arow] = av.y;
        sA[acol + 2][arow] = av.z; sA[acol + 3][arow] = av.w;
        *(float4*)(&sB[brow][bcol]) = bv;
        __syncthreads();
#pragma unroll
        for (int k = 0; k < 8; k++) {
            float ar[8], br[8];
            *(float4*)(ar)     = *(const float4*)(&sA[k][ty * 8]);
            *(float4*)(ar + 4) = *(const float4*)(&sA[k][ty * 8 + 4]);
            *(float4*)(br)     = *(const float4*)(&sB[k][tx * 8]);
            *(float4*)(br + 4) = *(const float4*)(&sB[k][tx * 8 + 4]);
#pragma unroll
            for (int i = 0; i < 8; i++)
#pragma unroll
                for (int j = 0; j < 8; j++)
                    acc[i][j] = fmaf(ar[i], br[j], acc[i][j]);
        }
        __syncthreads();
    }

#pragma unroll
    for (int i = 0; i < 8; i++) {
        int rg = srow[ty * 8 + i];
        if (rg < 0) continue;
#pragma unroll
        for (int j = 0; j < 8; j++) {
            int n = bn + tx * 8 + j;
            float v = acc[i][j] + zhb[tgrp * 512 + n];
            if (n < 256) v = fminf(fmaxf(v, -100.f), 100.f);           // z_loc
            else         v = fminf(softplus_f(v) + 0.001f, 100.f);     // z_scale
            out[(long)rg * OUTC + 11 + n] = v;
        }
    }
}

// ---------------- launch ----------------
extern "C" void kernel_launch(void* const* d_in, const int* in_sizes, int n_in,
                              void* d_out, int out_size)
{
    const float* x   = (const float*)d_in[0];
    const int*   t   = (const int*)  d_in[1];
    const float* yv  = (const float*)d_in[2];
    const float* dv  = (const float*)d_in[3];
    const float* tw0 = (const float*)d_in[4];
    const float* tb0 = (const float*)d_in[5];
    const float* tw1 = (const float*)d_in[6];
    const float* tb1 = (const float*)d_in[7];
    const float* tw2 = (const float*)d_in[8];
    const float* tb2 = (const float*)d_in[9];
    const float* yw0 = (const float*)d_in[10];
    const float* yb0 = (const float*)d_in[11];
    const float* yw1 = (const float*)d_in[12];
    const float* yb1 = (const float*)d_in[13];
    const float* yhW = (const float*)d_in[14];
    const float* yhb = (const float*)d_in[15];
    const float* dw0 = (const float*)d_in[16];
    const float* db0 = (const float*)d_in[17];
    const float* dw1 = (const float*)d_in[18];
    const float* db1 = (const float*)d_in[19];
    const float* dhW = (const float*)d_in[20];
    const float* dhb = (const float*)d_in[21];
    const float* zw0 = (const float*)d_in[22];
    const float* zb0 = (const float*)d_in[23];
    const float* zw1 = (const float*)d_in[24];
    const float* zb1 = (const float*)d_in[25];
    const float* zhW = (const float*)d_in[26];
    const float* zhb = (const float*)d_in[27];
    float* out = (float*)d_out;

    float* buf1 = nullptr;
    float* buf2 = nullptr;
    cudaGetSymbolAddress((void**)&buf1, g_buf1);
    cudaGetSymbolAddress((void**)&buf2, g_buf2);

    // ---- bucket rows by treatment t ----
    k_init<<<1, 32>>>();
    k_hist<<<(BATCH + 255) / 256, 256>>>(t);
    k_off<<<1, 32>>>();
    k_scatter<<<(BATCH + 255) / 256, 256>>>(t);

    const dim3 blk(256);
    const dim3 g1024(1024 / 128, BATCH / 128);  // N=1024
    const dim3 g256(256 / 128, BATCH / 128);    // N=256
    const int headBlocks = (BATCH * 32) / 256;  // one warp per row, 256 thr/blk

    // ---- t path ----
    sgemm<1, false><<<g256, blk>>>(x,    tw0, tb0, buf1, 256, 1024, nullptr, nullptr, nullptr);
    sgemm<1, false><<<g256, blk>>>(buf1, tw1, tb1, buf2, 256, 256,  nullptr, nullptr, nullptr);
    thead_kernel<<<headBlocks, blk>>>(buf2, tw2, tb2, out);

    // ---- y path ----
    sgemm<1, false><<<g1024, blk>>>(x,    yw0, yb0, buf1, 1024, 1024, nullptr, nullptr, nullptr);
    sgemm<1, false><<<g1024, blk>>>(buf1, yw1, yb1, buf2, 1024, 1024, nullptr, nullptr, nullptr);
    head2_kernel<<<headBlocks, blk>>>(buf2, t, yhW, yhb, out, 7);

    // ---- d path ----
    sgemm<1, false><<<g1024, blk>>>(x,    dw0, db0, buf1, 1024, 1024, nullptr, nullptr, nullptr);
    sgemm<1, false><<<g1024, blk>>>(buf1, dw1, db1, buf2, 1024, 1024, nullptr, nullptr, nullptr);
    head2_kernel<<<headBlocks, blk>>>(buf2, t, dhW, dhb, out, 9);

    // ---- z path: cat([y,d,x]) @ zw0 == x @ zw0[2:] + y*zw0[0] + d*zw0[1] ----
    sgemm<1, true ><<<g1024, blk>>>(x,    zw0 + 2 * 1024, zb0, buf1, 1024, 1024, yv, dv, zw0);
    sgemm<1, false><<<g1024, blk>>>(buf1, zw1, zb1, buf2, 1024, 1024, nullptr, nullptr, nullptr);
    zhead_kernel<<<dim3(512 / 128, BATCH / 128, 7), blk>>>(buf2, zhW, zhb, out);
}

// round 3
// speedup vs baseline: 2.9450x; 2.9450x over previous
#include <cuda_runtime.h>
#include <cuda_bf16.h>
#include <cstdint>
#include <math.h>

#define BATCH 16384
#define OUTC  523   // 7 + 4 + 512

// ========================= PTX helpers (sm_80-level only) =========================
__device__ __forceinline__ uint32_t smem_u32(const void* p) {
    uint32_t a;
    asm("{ .reg .u64 t; cvta.to.shared.u64 t, %1; cvt.u32.u64 %0, t; }" : "=r"(a) : "l"(p));
    return a;
}
__device__ __forceinline__ void cp16(uint32_t saddr, const void* g) {
    asm volatile("cp.async.cg.shared.global [%0], [%1], 16;" :: "r"(saddr), "l"(g));
}
#define CP_COMMIT() asm volatile("cp.async.commit_group;" ::: "memory")
#define CP_WAIT(n)  asm volatile("cp.async.wait_group %0;" :: "n"(n) : "memory")

__device__ __forceinline__ void ldmx4(uint32_t& r0, uint32_t& r1, uint32_t& r2, uint32_t& r3, uint32_t addr) {
    asm volatile("ldmatrix.sync.aligned.m8n8.x4.shared.b16 {%0,%1,%2,%3}, [%4];"
                 : "=r"(r0), "=r"(r1), "=r"(r2), "=r"(r3) : "r"(addr));
}
__device__ __forceinline__ void mma16816(float* c, const uint32_t* a, uint32_t b0, uint32_t b1) {
    asm volatile("mma.sync.aligned.m16n8k16.row.col.f32.bf16.bf16.f32 "
                 "{%0,%1,%2,%3}, {%4,%5,%6,%7}, {%8,%9}, {%0,%1,%2,%3};"
                 : "+f"(c[0]), "+f"(c[1]), "+f"(c[2]), "+f"(c[3])
                 : "r"(a[0]), "r"(a[1]), "r"(a[2]), "r"(a[3]), "r"(b0), "r"(b1));
}
__device__ __forceinline__ uint32_t swz(uint32_t off) { return off ^ ((off >> 3) & 0x70); }

// ========================= scratch =========================
__device__ __nv_bfloat16 g_xhi[BATCH * 1024];
__device__ __nv_bfloat16 g_xlo[BATCH * 1024];
__device__ __nv_bfloat16 g_a1hi[BATCH * 1024];
__device__ __nv_bfloat16 g_a1lo[BATCH * 1024];
__device__ __nv_bfloat16 g_a2hi[BATCH * 1024];
__device__ __nv_bfloat16 g_a2lo[BATCH * 1024];
__device__ float         g_f32[BATCH * 1024];
__device__ __nv_bfloat16 g_whi[10300000];
__device__ __nv_bfloat16 g_wlo[10300000];
__device__ int g_ridx[BATCH];
__device__ int g_cnt[8];
__device__ int g_off[8];
__device__ int g_cur[8];

// weight-pool offsets (elements)
#define OFF_TW0 0
#define OFF_TW1 262144
#define OFF_YW0 327680
#define OFF_YW1 1376256
#define OFF_DW0 2424832
#define OFF_DW1 3473408
#define OFF_ZW0 4521984
#define OFF_ZW1 5570560
#define OFF_ZHW 6619136   // + t*524288

__device__ __forceinline__ float elu_f(float v) { return v > 0.f ? v : expm1f(v); }
__device__ __forceinline__ float softplus_f(float v) {
    return fmaxf(v, 0.f) + log1pf(expf(-fabsf(v)));
}

// ========================= preprocessing =========================
__global__ void xsplit_kernel(const float* __restrict__ x, __nv_bfloat16* __restrict__ hi,
                              __nv_bfloat16* __restrict__ lo, int n) {
    int i = blockIdx.x * blockDim.x + threadIdx.x;
    if (i < n) {
        float v = x[i];
        __nv_bfloat16 h = __float2bfloat16(v);
        hi[i] = h;
        lo[i] = __float2bfloat16(v - __bfloat162float(h));
    }
}
// transpose + split: W [Kd, N] fp32 -> Wt_hi/lo [N, Kd] bf16
__global__ void wsplit_kernel(const float* __restrict__ W, __nv_bfloat16* __restrict__ hi,
                              __nv_bfloat16* __restrict__ lo, int Kd, int N) {
    __shared__ float tile[32][33];
    int n0 = blockIdx.x * 32, k0 = blockIdx.y * 32;
    int tx = threadIdx.x, ty = threadIdx.y; // 32 x 8
    for (int i = ty; i < 32; i += 8)
        tile[i][tx] = W[(size_t)(k0 + i) * N + n0 + tx];
    __syncthreads();
    for (int i = ty; i < 32; i += 8) {
        float v = tile[tx][i];  // = W[k0+tx][n0+i]
        size_t o = (size_t)(n0 + i) * Kd + k0 + tx;
        __nv_bfloat16 h = __float2bfloat16(v);
        hi[o] = h;
        lo[o] = __float2bfloat16(v - __bfloat162float(h));
    }
}

// ========================= bucketing by t =========================
__global__ void k_init() { if (threadIdx.x < 8) g_cnt[threadIdx.x] = 0; }
__global__ void k_hist(const int* __restrict__ t) {
    int i = blockIdx.x * blockDim.x + threadIdx.x;
    if (i < BATCH) atomicAdd(&g_cnt[t[i]], 1);
}
__global__ void k_off() {
    if (threadIdx.x == 0) {
        int s = 0;
        for (int i = 0; i < 7; i++) { g_off[i] = s; g_cur[i] = s; s += g_cnt[i]; }
    }
}
__global__ void k_scatter(const int* __restrict__ t) {
    int i = blockIdx.x * blockDim.x + threadIdx.x;
    if (i < BATCH) { int p = atomicAdd(&g_cur[t[i]], 1); g_ridx[p] = i; }
}

// ========================= 3xBF16 mma.sync GEMM =========================
// C[M,N] = elu(A @ Wt^T + bias [+ y*wyd0 + d*wyd1])
// A: hi/lo bf16 [M,Kd] row-major; Wt: hi/lo bf16 [N,Kd] row-major (== W col-major)
// CTA tile 128x128, K-chunk 64 bf16, 8 warps each 32(m) x 64(n), double-buffered cp.async.
#define S_AH 0
#define S_AL 16384
#define S_BH 32768
#define S_BL 49152
#define STAGE_SZ 65536
#define SMEM_REQ 133120   // 2 stages + srow + align pad

// per-warp compute over one resident K-chunk (64) in stage `st` (smem uint32 base addr)
__device__ __forceinline__ void compute_chunk(uint32_t st, int warp_m, int warp_n, int lane,
                                              float acc[2][8][4])
{
    const int lrow = lane & 7;
    const int lmat = lane >> 3;
#pragma unroll
    for (int ks = 0; ks < 4; ks++) {
        uint32_t bh[16], bl[16];
#pragma unroll
        for (int p = 0; p < 4; p++) {
            int ntile = p * 2 + (lmat >> 1);
            int half = lmat & 1;
            uint32_t off = (uint32_t)((warp_n * 64 + ntile * 8 + lrow) * 128 + (ks * 16 + half * 8) * 2);
            uint32_t a = swz(off);
            ldmx4(bh[p * 4 + 0], bh[p * 4 + 1], bh[p * 4 + 2], bh[p * 4 + 3], st + S_BH + a);
            ldmx4(bl[p * 4 + 0], bl[p * 4 + 1], bl[p * 4 + 2], bl[p * 4 + 3], st + S_BL + a);
        }
#pragma unroll
        for (int mt = 0; mt < 2; mt++) {
            uint32_t ah[4], al[4];
            uint32_t off = (uint32_t)((warp_m * 32 + mt * 16 + (lmat & 1) * 8 + lrow) * 128
                                      + (ks * 16 + (lmat >> 1) * 8) * 2);
            uint32_t a = swz(off);
            ldmx4(ah[0], ah[1], ah[2], ah[3], st + S_AH + a);
            ldmx4(al[0], al[1], al[2], al[3], st + S_AL + a);
#pragma unroll
            for (int nt = 0; nt < 8; nt++) {
                mma16816(acc[mt][nt], ah, bh[nt * 2], bh[nt * 2 + 1]);
                mma16816(acc[mt][nt], ah, bl[nt * 2], bl[nt * 2 + 1]);
                mma16816(acc[mt][nt], al, bh[nt * 2], bh[nt * 2 + 1]);
            }
        }
    }
}

template<bool ADD_YD, bool OUT_F32>
__global__ void __launch_bounds__(256, 1)
gemm3bf(const __nv_bfloat16* __restrict__ Ahi, const __nv_bfloat16* __restrict__ Alo,
        const __nv_bfloat16* __restrict__ Bhi, const __nv_bfloat16* __restrict__ Blo,
        const float* __restrict__ bias, int N, int Kd,
        float* __restrict__ outF, __nv_bfloat16* __restrict__ outHi, __nv_bfloat16* __restrict__ outLo,
        const float* __restrict__ yv, const float* __restrict__ dv, const float* __restrict__ wyd)
{
    extern __shared__ char smraw[];
    uint32_t sb = smem_u32(smraw);
    uint32_t ab = (sb + 1023u) & ~1023u;

    const int tid = threadIdx.x;
    const int wid = tid >> 5;
    const int lane = tid & 31;
    const int warp_m = wid & 3;
    const int warp_n = wid >> 2;
    const int bm = blockIdx.y * 128, bn = blockIdx.x * 128;

    const int lr = tid >> 3;          // loader row 0..127 per 2 c-steps... (c>>3)
    const int nc = Kd >> 6;

    float acc[2][8][4];
#pragma unroll
    for (int i = 0; i < 2; i++)
#pragma unroll
        for (int j = 0; j < 8; j++)
#pragma unroll
            for (int q = 0; q < 4; q++) acc[i][j][q] = 0.f;
    (void)lr;

    // ---- loader lambda ----
    auto load_chunk = [&](int ch, int stg) {
        uint32_t st = ab + stg * STAGE_SZ;
        int k0 = ch * 64;
#pragma unroll
        for (int c = tid; c < 1024; c += 256) {
            int r = c >> 3, cc = c & 7;
            uint32_t sw = swz((uint32_t)(r * 128 + cc * 16));
            size_t ga = (size_t)(bm + r) * Kd + k0 + cc * 8;
            cp16(st + S_AH + sw, Ahi + ga);
            cp16(st + S_AL + sw, Alo + ga);
            size_t gb = (size_t)(bn + r) * Kd + k0 + cc * 8;
            cp16(st + S_BH + sw, Bhi + gb);
            cp16(st + S_BL + sw, Blo + gb);
        }
    };

    load_chunk(0, 0);
    CP_COMMIT();
    for (int ch = 0; ch < nc; ch++) {
        int cur = ch & 1;
        if (ch + 1 < nc) {
            load_chunk(ch + 1, cur ^ 1);
            CP_COMMIT();
            CP_WAIT(1);
        } else {
            CP_WAIT(0);
        }
        __syncthreads();
        compute_chunk(ab + cur * STAGE_SZ, warp_m, warp_n, lane, acc);
        __syncthreads();
    }

    // ---- epilogue ----
    const int tgm = lane >> 2;
    const int tgn = (lane & 3) * 2;
#pragma unroll
    for (int mt = 0; mt < 2; mt++) {
#pragma unroll
        for (int dh = 0; dh < 2; dh++) {
            int m = bm + warp_m * 32 + mt * 16 + tgm + dh * 8;
            float ya = 0.f, da = 0.f;
            if (ADD_YD) { ya = __ldg(yv + m); da = __ldg(dv + m); }
#pragma unroll
            for (int nt = 0; nt < 8; nt++) {
                int n = bn + warp_n * 64 + nt * 8 + tgn;
                float v0 = acc[mt][nt][dh * 2 + 0];
                float v1 = acc[mt][nt][dh * 2 + 1];
                float2 bb = *(const float2*)(bias + n);
                v0 += bb.x; v1 += bb.y;
                if (ADD_YD) {
                    float2 w0 = *(const float2*)(wyd + n);
                    float2 w1 = *(const float2*)(wyd + N + n);
                    v0 += ya * w0.x + da * w1.x;
                    v1 += ya * w0.y + da * w1.y;
                }
                v0 = elu_f(v0); v1 = elu_f(v1);
                if (OUT_F32) {
                    *(float2*)(outF + (size_t)m * N + n) = make_float2(v0, v1);
                } else {
                    __nv_bfloat16 h0 = __float2bfloat16(v0);
                    __nv_bfloat16 h1 = __float2bfloat16(v1);
                    __nv_bfloat162 hp; hp.x = h0; hp.y = h1;
                    __nv_bfloat162 lp;
                    lp.x = __float2bfloat16(v0 - __bfloat162float(h0));
                    lp.y = __float2bfloat16(v1 - __bfloat162float(h1));
                    *(__nv_bfloat162*)(outHi + (size_t)m * N + n) = hp;
                    *(__nv_bfloat162*)(outLo + (size_t)m * N + n) = lp;
                }
            }
        }
    }
}

// ========================= z head: gathered grouped GEMM =========================
__global__ void __launch_bounds__(256, 1)
zheadmma(const __nv_bfloat16* __restrict__ Ahi, const __nv_bfloat16* __restrict__ Alo,
         const __nv_bfloat16* __restrict__ Whi, const __nv_bfloat16* __restrict__ Wlo,
         const float* __restrict__ zhb, float* __restrict__ out)
{
    const int grp = blockIdx.z;
    const int cnt = g_cnt[grp];
    const int m0 = blockIdx.y * 128;
    if (m0 >= cnt) return;
    const int base = g_off[grp];
    const int bn = blockIdx.x * 128;

    extern __shared__ char smraw[];
    uint32_t sb = smem_u32(smraw);
    uint32_t ab = (sb + 1023u) & ~1023u;
    char* sm = smraw + (ab - sb);
    int* srow = (int*)(sm + 2 * STAGE_SZ);

    const int tid = threadIdx.x;
    const int wid = tid >> 5;
    const int lane = tid & 31;
    const int warp_m = wid & 3;
    const int warp_n = wid >> 2;

    if (tid < 128) {
        int mi = m0 + tid;
        srow[tid] = (mi < cnt) ? g_ridx[base + mi] : -1;
    }
    __syncthreads();
    const int safe0 = srow[0];

    const __nv_bfloat16* Wg_hi = Whi + (size_t)grp * 512 * 1024;
    const __nv_bfloat16* Wg_lo = Wlo + (size_t)grp * 512 * 1024;

    float acc[2][8][4];
#pragma unroll
    for (int i = 0; i < 2; i++)
#pragma unroll
        for (int j = 0; j < 8; j++)
#pragma unroll
            for (int q = 0; q < 4; q++) acc[i][j][q] = 0.f;

    auto load_chunk = [&](int ch, int stg) {
        uint32_t st = ab + stg * STAGE_SZ;
        int k0 = ch * 64;
#pragma unroll
        for (int c = tid; c < 1024; c += 256) {
            int r = c >> 3, cc = c & 7;
            uint32_t sw = swz((uint32_t)(r * 128 + cc * 16));
            int gr = srow[r]; if (gr < 0) gr = safe0;
            size_t ga = (size_t)gr * 1024 + k0 + cc * 8;
            cp16(st + S_AH + sw, Ahi + ga);
            cp16(st + S_AL + sw, Alo + ga);
            size_t gb = (size_t)(bn + r) * 1024 + k0 + cc * 8;
            cp16(st + S_BH + sw, Wg_hi + gb);
            cp16(st + S_BL + sw, Wg_lo + gb);
        }
    };

    load_chunk(0, 0);
    CP_COMMIT();
    for (int ch = 0; ch < 16; ch++) {
        int cur = ch & 1;
        if (ch + 1 < 16) {
            load_chunk(ch + 1, cur ^ 1);
            CP_COMMIT();
            CP_WAIT(1);
        } else {
            CP_WAIT(0);
        }
        __syncthreads();
        compute_chunk(ab + cur * STAGE_SZ, warp_m, warp_n, lane, acc);
        __syncthreads();
    }

    const int tgm = lane >> 2;
    const int tgn = (lane & 3) * 2;
#pragma unroll
    for (int mt = 0; mt < 2; mt++) {
#pragma unroll
        for (int dh = 0; dh < 2; dh++) {
            int mloc = warp_m * 32 + mt * 16 + tgm + dh * 8;
            int rg = srow[mloc];
            if (rg < 0) continue;
            float* op = out + (size_t)rg * OUTC + 11;
#pragma unroll
            for (int nt = 0; nt < 8; nt++) {
                int n = bn + warp_n * 64 + nt * 8 + tgn;
                float v0 = acc[mt][nt][dh * 2 + 0] + __ldg(zhb + grp * 512 + n);
                float v1 = acc[mt][nt][dh * 2 + 1] + __ldg(zhb + grp * 512 + n + 1);
                if (n < 256) {
                    v0 = fminf(fmaxf(v0, -100.f), 100.f);
                    v1 = fminf(fmaxf(v1, -100.f), 100.f);
                } else {
                    v0 = fminf(softplus_f(v0) + 0.001f, 100.f);
                    v1 = fminf(softplus_f(v1) + 0.001f, 100.f);
                }
                op[n] = v0;
                op[n + 1] = v1;
            }
        }
    }
}

// ========================= small head kernels (fp32) =========================
__global__ void thead_kernel(const float* __restrict__ hid, const float* __restrict__ tw2,
                             const float* __restrict__ tb2, float* __restrict__ out)
{
    int w = (blockIdx.x * blockDim.x + threadIdx.x) >> 5;
    int lane = threadIdx.x & 31;
    if (w >= BATCH) return;
    const float* hr = hid + (size_t)w * 256;
    float acc[7] = {0.f, 0.f, 0.f, 0.f, 0.f, 0.f, 0.f};
    for (int k = lane; k < 256; k += 32) {
        float h = hr[k];
        const float* wr = tw2 + k * 7;
#pragma unroll
        for (int j = 0; j < 7; j++) acc[j] = fmaf(h, wr[j], acc[j]);
    }
#pragma unroll
    for (int j = 0; j < 7; j++)
        for (int o = 16; o > 0; o >>= 1) acc[j] += __shfl_xor_sync(0xffffffffu, acc[j], o);
    if (lane == 0) {
#pragma unroll
        for (int j = 0; j < 7; j++) {
            float v = elu_f(acc[j] + tb2[j]);
            out[(size_t)w * OUTC + j] = fminf(fmaxf(v, -10.f), 10.f);
        }
    }
}
__global__ void head2_kernel(const float* __restrict__ hid, const int* __restrict__ t,
                             const float* __restrict__ hW, const float* __restrict__ hb,
                             float* __restrict__ out, int col0)
{
    int w = (blockIdx.x * blockDim.x + threadIdx.x) >> 5;
    int lane = threadIdx.x & 31;
    if (w >= BATCH) return;
    int tt = t[w];
    const float*  hr = hid + (size_t)w * 1024;
    const float2* wp = (const float2*)(hW + (size_t)tt * 2048);
    float a0 = 0.f, a1 = 0.f;
    for (int k = lane; k < 1024; k += 32) {
        float h = hr[k];
        float2 ww = wp[k];
        a0 = fmaf(h, ww.x, a0);
        a1 = fmaf(h, ww.y, a1);
    }
    for (int o = 16; o > 0; o >>= 1) {
        a0 += __shfl_xor_sync(0xffffffffu, a0, o);
        a1 += __shfl_xor_sync(0xffffffffu, a1, o);
    }
    if (lane == 0) {
        float loc = fminf(fmaxf(a0 + hb[tt * 2 + 0], -1e6f), 1e6f);
        float sc  = fminf(softplus_f(a1 + hb[tt * 2 + 1]) + 1e-3f, 1e6f);
        out[(size_t)w * OUTC + col0]     = loc;
        out[(size_t)w * OUTC + col0 + 1] = sc;
    }
}

// ========================= launch =========================
extern "C" void kernel_launch(void* const* d_in, const int* in_sizes, int n_in,
                              void* d_out, int out_size)
{
    const float* x   = (const float*)d_in[0];
    const int*   t   = (const int*)  d_in[1];
    const float* yv  = (const float*)d_in[2];
    const float* dv  = (const float*)d_in[3];
    const float* tw0 = (const float*)d_in[4];
    const float* tb0 = (const float*)d_in[5];
    const float* tw1 = (const float*)d_in[6];
    const float* tb1 = (const float*)d_in[7];
    const float* tw2 = (const float*)d_in[8];
    const float* tb2 = (const float*)d_in[9];
    const float* yw0 = (const float*)d_in[10];
    const float* yb0 = (const float*)d_in[11];
    const float* yw1 = (const float*)d_in[12];
    const float* yb1 = (const float*)d_in[13];
    const float* yhW = (const float*)d_in[14];
    const float* yhb = (const float*)d_in[15];
    const float* dw0 = (const float*)d_in[16];
    const float* db0 = (const float*)d_in[17];
    const float* dw1 = (const float*)d_in[18];
    const float* db1 = (const float*)d_in[19];
    const float* dhW = (const float*)d_in[20];
    const float* dhb = (const float*)d_in[21];
    const float* zw0 = (const float*)d_in[22];
    const float* zb0 = (const float*)d_in[23];
    const float* zw1 = (const float*)d_in[24];
    const float* zb1 = (const float*)d_in[25];
    const float* zhW = (const float*)d_in[26];
    const float* zhb = (const float*)d_in[27];
    float* out = (float*)d_out;

    __nv_bfloat16 *xhi, *xlo, *a1hi, *a1lo, *a2hi, *a2lo, *whi, *wlo;
    float* f32buf;
    cudaGetSymbolAddress((void**)&xhi, g_xhi);
    cudaGetSymbolAddress((void**)&xlo, g_xlo);
    cudaGetSymbolAddress((void**)&a1hi, g_a1hi);
    cudaGetSymbolAddress((void**)&a1lo, g_a1lo);
    cudaGetSymbolAddress((void**)&a2hi, g_a2hi);
    cudaGetSymbolAddress((void**)&a2lo, g_a2lo);
    cudaGetSymbolAddress((void**)&whi, g_whi);
    cudaGetSymbolAddress((void**)&wlo, g_wlo);
    cudaGetSymbolAddress((void**)&f32buf, g_f32);

    cudaFuncSetAttribute((const void*)gemm3bf<false, false>, cudaFuncAttributeMaxDynamicSharedMemorySize, SMEM_REQ);
    cudaFuncSetAttribute((const void*)gemm3bf<false, true>,  cudaFuncAttributeMaxDynamicSharedMemorySize, SMEM_REQ);
    cudaFuncSetAttribute((const void*)gemm3bf<true, false>,  cudaFuncAttributeMaxDynamicSharedMemorySize, SMEM_REQ);
    cudaFuncSetAttribute((const void*)zheadmma,               cudaFuncAttributeMaxDynamicSharedMemorySize, SMEM_REQ);

    // ---- bucketing by t ----
    k_init<<<1, 32>>>();
    k_hist<<<(BATCH + 255) / 256, 256>>>(t);
    k_off<<<1, 32>>>();
    k_scatter<<<(BATCH + 255) / 256, 256>>>(t);

    // ---- preprocessing: split x, transpose+split weights ----
    {
        int n = BATCH * 1024;
        xsplit_kernel<<<(n + 255) / 256, 256>>>(x, xhi, xlo, n);
        dim3 tb(32, 8);
        wsplit_kernel<<<dim3(256 / 32, 1024 / 32), tb>>>(tw0, whi + OFF_TW0, wlo + OFF_TW0, 1024, 256);
        wsplit_kernel<<<dim3(256 / 32, 256 / 32),  tb>>>(tw1, whi + OFF_TW1, wlo + OFF_TW1, 256, 256);
        wsplit_kernel<<<dim3(1024 / 32, 1024 / 32), tb>>>(yw0, whi + OFF_YW0, wlo + OFF_YW0, 1024, 1024);
        wsplit_kernel<<<dim3(1024 / 32, 1024 / 32), tb>>>(yw1, whi + OFF_YW1, wlo + OFF_YW1, 1024, 1024);
        wsplit_kernel<<<dim3(1024 / 32, 1024 / 32), tb>>>(dw0, whi + OFF_DW0, wlo + OFF_DW0, 1024, 1024);
        wsplit_kernel<<<dim3(1024 / 32, 1024 / 32), tb>>>(dw1, whi + OFF_DW1, wlo + OFF_DW1, 1024, 1024);
        wsplit_kernel<<<dim3(1024 / 32, 1024 / 32), tb>>>(zw0 + 2 * 1024, whi + OFF_ZW0, wlo + OFF_ZW0, 1024, 1024);
        wsplit_kernel<<<dim3(1024 / 32, 1024 / 32), tb>>>(zw1, whi + OFF_ZW1, wlo + OFF_ZW1, 1024, 1024);
        for (int g = 0; g < 7; g++)
            wsplit_kernel<<<dim3(512 / 32, 1024 / 32), tb>>>(zhW + (size_t)g * 1024 * 512,
                whi + OFF_ZHW + (size_t)g * 524288, wlo + OFF_ZHW + (size_t)g * 524288, 1024, 512);
    }

    const dim3 blk(256);
    const dim3 g1024(1024 / 128, BATCH / 128);
    const dim3 g256(256 / 128, BATCH / 128);
    const int headBlocks = (BATCH * 32) / 256;

    // ---- t path ----
    gemm3bf<false, false><<<g256, blk, SMEM_REQ>>>(xhi, xlo, whi + OFF_TW0, wlo + OFF_TW0, tb0,
        256, 1024, nullptr, a1hi, a1lo, nullptr, nullptr, nullptr);
    gemm3bf<false, true><<<g256, blk, SMEM_REQ>>>(a1hi, a1lo, whi + OFF_TW1, wlo + OFF_TW1, tb1,
        256, 256, f32buf, nullptr, nullptr, nullptr, nullptr, nullptr);
    thead_kernel<<<headBlocks, blk>>>(f32buf, tw2, tb2, out);

    // ---- y path ----
    gemm3bf<false, false><<<g1024, blk, SMEM_REQ>>>(xhi, xlo, whi + OFF_YW0, wlo + OFF_YW0, yb0,
        1024, 1024, nullptr, a1hi, a1lo, nullptr, nullptr, nullptr);
    gemm3bf<false, true><<<g1024, blk, SMEM_REQ>>>(a1hi, a1lo, whi + OFF_YW1, wlo + OFF_YW1, yb1,
        1024, 1024, f32buf, nullptr, nullptr, nullptr, nullptr, nullptr);
    head2_kernel<<<headBlocks, blk>>>(f32buf, t, yhW, yhb, out, 7);

    // ---- d path ----
    gemm3bf<false, false><<<g1024, blk, SMEM_REQ>>>(xhi, xlo, whi + OFF_DW0, wlo + OFF_DW0, db0,
        1024, 1024, nullptr, a1hi, a1lo, nullptr, nullptr, nullptr);
    gemm3bf<false, true><<<g1024, blk, SMEM_REQ>>>(a1hi, a1lo, whi + OFF_DW1, wlo + OFF_DW1, db1,
        1024, 1024, f32buf, nullptr, nullptr, nullptr, nullptr, nullptr);
    head2_kernel<<<headBlocks, blk>>>(f32buf, t, dhW, dhb, out, 9);

    // ---- z path (cat([y,d,x]) folded into epilogue rank-2 update) ----
    gemm3bf<true, false><<<g1024, blk, SMEM_REQ>>>(xhi, xlo, whi + OFF_ZW0, wlo + OFF_ZW0, zb0,
        1024, 1024, nullptr, a1hi, a1lo, yv, dv, zw0);
    gemm3bf<false, false><<<g1024, blk, SMEM_REQ>>>(a1hi, a1lo, whi + OFF_ZW1, wlo + OFF_ZW1, zb1,
        1024, 1024, nullptr, a2hi, a2lo, nullptr, nullptr, nullptr);
    zheadmma<<<dim3(512 / 128, BATCH / 128, 7), blk, SMEM_REQ>>>(a2hi, a2lo,
        whi + OFF_ZHW, wlo + OFF_ZHW, zhb, out);
}

// round 4
// speedup vs baseline: 3.1649x; 1.0747x over previous
#include <cuda_runtime.h>
#include <cuda_bf16.h>
#include <cstdint>
#include <math.h>

#define BATCH 16384
#define OUTC  523   // 7 + 4 + 512

// ========================= PTX helpers (sm_80-level only) =========================
__device__ __forceinline__ uint32_t smem_u32(const void* p) {
    uint32_t a;
    asm("{ .reg .u64 t; cvta.to.shared.u64 t, %1; cvt.u32.u64 %0, t; }" : "=r"(a) : "l"(p));
    return a;
}
__device__ __forceinline__ void cp16(uint32_t saddr, const void* g) {
    asm volatile("cp.async.cg.shared.global [%0], [%1], 16;" :: "r"(saddr), "l"(g));
}
#define CP_COMMIT() asm volatile("cp.async.commit_group;" ::: "memory")
#define CP_WAIT(n)  asm volatile("cp.async.wait_group %0;" :: "n"(n) : "memory")

__device__ __forceinline__ void ldmx4(uint32_t& r0, uint32_t& r1, uint32_t& r2, uint32_t& r3, uint32_t addr) {
    asm volatile("ldmatrix.sync.aligned.m8n8.x4.shared.b16 {%0,%1,%2,%3}, [%4];"
                 : "=r"(r0), "=r"(r1), "=r"(r2), "=r"(r3) : "r"(addr));
}
__device__ __forceinline__ void mma16816(float* c, const uint32_t* a, uint32_t b0, uint32_t b1) {
    asm volatile("mma.sync.aligned.m16n8k16.row.col.f32.bf16.bf16.f32 "
                 "{%0,%1,%2,%3}, {%4,%5,%6,%7}, {%8,%9}, {%0,%1,%2,%3};"
                 : "+f"(c[0]), "+f"(c[1]), "+f"(c[2]), "+f"(c[3])
                 : "r"(a[0]), "r"(a[1]), "r"(a[2]), "r"(a[3]), "r"(b0), "r"(b1));
}
__device__ __forceinline__ uint32_t swz(uint32_t off) { return off ^ ((off >> 3) & 0x70); }

// ========================= scratch =========================
__device__ __nv_bfloat16 g_xhi[BATCH * 1024];
__device__ __nv_bfloat16 g_xlo[BATCH * 1024];
__device__ __nv_bfloat16 g_a1hi[BATCH * 1024];
__device__ __nv_bfloat16 g_a1lo[BATCH * 1024];
__device__ __nv_bfloat16 g_a2hi[BATCH * 1024];
__device__ __nv_bfloat16 g_a2lo[BATCH * 1024];
__device__ float         g_f32[BATCH * 1024];
__device__ __nv_bfloat16 g_whi[10300000];
__device__ __nv_bfloat16 g_wlo[10300000];
__device__ int g_ridx[BATCH];
__device__ int g_cnt[8];
__device__ int g_off[8];
__device__ int g_cur[8];

// weight-pool offsets (elements)
#define OFF_TW0 0
#define OFF_TW1 262144
#define OFF_YW0 327680
#define OFF_YW1 1376256
#define OFF_DW0 2424832
#define OFF_DW1 3473408
#define OFF_ZW0 4521984
#define OFF_ZW1 5570560
#define OFF_ZHW 6619136   // + t*524288

__device__ __forceinline__ float elu_f(float v) { return v > 0.f ? v : expm1f(v); }
__device__ __forceinline__ float softplus_f(float v) {
    return fmaxf(v, 0.f) + log1pf(expf(-fabsf(v)));
}

// ========================= preprocessing =========================
__global__ void xsplit_kernel(const float* __restrict__ x, __nv_bfloat16* __restrict__ hi,
                              __nv_bfloat16* __restrict__ lo, int n) {
    int i = blockIdx.x * blockDim.x + threadIdx.x;
    if (i < n) {
        float v = x[i];
        __nv_bfloat16 h = __float2bfloat16(v);
        hi[i] = h;
        lo[i] = __float2bfloat16(v - __bfloat162float(h));
    }
}
// transpose + split one 32x32 tile of W [Kd,N] -> Wt [N,Kd]
__device__ __forceinline__ void wsplit_tile(const float* __restrict__ W,
                                            __nv_bfloat16* __restrict__ hi,
                                            __nv_bfloat16* __restrict__ lo,
                                            int Kd, int N, int n0, int k0,
                                            float tile[32][33], int tx, int ty) {
    for (int i = ty; i < 32; i += 8)
        tile[i][tx] = W[(size_t)(k0 + i) * N + n0 + tx];
    __syncthreads();
    for (int i = ty; i < 32; i += 8) {
        float v = tile[tx][i];  // = W[k0+tx][n0+i]
        size_t o = (size_t)(n0 + i) * Kd + k0 + tx;
        __nv_bfloat16 h = __float2bfloat16(v);
        hi[o] = h;
        lo[o] = __float2bfloat16(v - __bfloat162float(h));
    }
}
__global__ void wsplit_kernel(const float* __restrict__ W, __nv_bfloat16* __restrict__ hi,
                              __nv_bfloat16* __restrict__ lo, int Kd, int N) {
    __shared__ float tile[32][33];
    wsplit_tile(W, hi, lo, Kd, N, blockIdx.x * 32, blockIdx.y * 32, tile, threadIdx.x, threadIdx.y);
}
struct Ptr6 { const float* p[6]; size_t off[6]; };
// six 1024x1024 matrices in one launch
__global__ void wsplit6_kernel(Ptr6 tab, __nv_bfloat16* __restrict__ hi, __nv_bfloat16* __restrict__ lo) {
    __shared__ float tile[32][33];
    int z = blockIdx.z;
    wsplit_tile(tab.p[z], hi + tab.off[z], lo + tab.off[z], 1024, 1024,
                blockIdx.x * 32, blockIdx.y * 32, tile, threadIdx.x, threadIdx.y);
}
// seven zhW groups [1024,512] in one launch
__global__ void wsplitz_kernel(const float* __restrict__ zhW,
                               __nv_bfloat16* __restrict__ hi, __nv_bfloat16* __restrict__ lo) {
    __shared__ float tile[32][33];
    int g = blockIdx.z;
    wsplit_tile(zhW + (size_t)g * 1024 * 512,
                hi + OFF_ZHW + (size_t)g * 524288, lo + OFF_ZHW + (size_t)g * 524288,
                1024, 512, blockIdx.x * 32, blockIdx.y * 32, tile, threadIdx.x, threadIdx.y);
}

// ========================= bucketing by t =========================
__global__ void k_init() { if (threadIdx.x < 8) g_cnt[threadIdx.x] = 0; }
__global__ void k_hist(const int* __restrict__ t) {
    int i = blockIdx.x * blockDim.x + threadIdx.x;
    if (i < BATCH) atomicAdd(&g_cnt[t[i]], 1);
}
__global__ void k_off() {
    if (threadIdx.x == 0) {
        int s = 0;
        for (int i = 0; i < 7; i++) { g_off[i] = s; g_cur[i] = s; s += g_cnt[i]; }
    }
}
__global__ void k_scatter(const int* __restrict__ t) {
    int i = blockIdx.x * blockDim.x + threadIdx.x;
    if (i < BATCH) { int p = atomicAdd(&g_cur[t[i]], 1); g_ridx[p] = i; }
}

// ========================= 3xBF16 mma.sync GEMM =========================
// CTA tile 128x128, K-chunk 64, 512 threads = 16 warps, warp tile 32x32,
// 3-stage cp.async pipeline, ONE __syncthreads per chunk.
#define S_AH 0
#define S_AL 16384
#define S_BH 32768
#define S_BL 49152
#define STAGE_SZ 65536
#define SMEM_REQ 198144   // align pad + 3 stages + srow

// per-warp compute over one K-chunk (64) at stage base `st`
__device__ __forceinline__ void compute_chunk(uint32_t st, int warp_m, int warp_n, int lane,
                                              float acc[2][4][4])
{
    const int lrow = lane & 7;
    const int lmat = lane >> 3;
#pragma unroll
    for (int ks = 0; ks < 4; ks++) {
        uint32_t bh[8], bl[8];
#pragma unroll
        for (int p = 0; p < 2; p++) {
            int ntile = p * 2 + (lmat >> 1);
            int half = lmat & 1;
            uint32_t off = (uint32_t)((warp_n * 32 + ntile * 8 + lrow) * 128 + (ks * 16 + half * 8) * 2);
            uint32_t a = swz(off);
            ldmx4(bh[p * 4 + 0], bh[p * 4 + 1], bh[p * 4 + 2], bh[p * 4 + 3], st + S_BH + a);
            ldmx4(bl[p * 4 + 0], bl[p * 4 + 1], bl[p * 4 + 2], bl[p * 4 + 3], st + S_BL + a);
        }
#pragma unroll
        for (int mt = 0; mt < 2; mt++) {
            uint32_t ah[4], al[4];
            uint32_t off = (uint32_t)((warp_m * 32 + mt * 16 + (lmat & 1) * 8 + lrow) * 128
                                      + (ks * 16 + (lmat >> 1) * 8) * 2);
            uint32_t a = swz(off);
            ldmx4(ah[0], ah[1], ah[2], ah[3], st + S_AH + a);
            ldmx4(al[0], al[1], al[2], al[3], st + S_AL + a);
#pragma unroll
            for (int nt = 0; nt < 4; nt++) {
                mma16816(acc[mt][nt], ah, bh[nt * 2], bh[nt * 2 + 1]);
                mma16816(acc[mt][nt], ah, bl[nt * 2], bl[nt * 2 + 1]);
                mma16816(acc[mt][nt], al, bh[nt * 2], bh[nt * 2 + 1]);
            }
        }
    }
}

template<bool ADD_YD, bool OUT_F32>
__global__ void __launch_bounds__(512, 1)
gemm3bf(const __nv_bfloat16* __restrict__ Ahi, const __nv_bfloat16* __restrict__ Alo,
        const __nv_bfloat16* __restrict__ Bhi, const __nv_bfloat16* __restrict__ Blo,
        const float* __restrict__ bias, int N, int Kd,
        float* __restrict__ outF, __nv_bfloat16* __restrict__ outHi, __nv_bfloat16* __restrict__ outLo,
        const float* __restrict__ yv, const float* __restrict__ dv, const float* __restrict__ wyd)
{
    extern __shared__ char smraw[];
    uint32_t sb = smem_u32(smraw);
    uint32_t ab = (sb + 1023u) & ~1023u;

    const int tid = threadIdx.x;
    const int wid = tid >> 5;
    const int lane = tid & 31;
    const int warp_m = wid & 3;
    const int warp_n = wid >> 2;
    const int bm = blockIdx.y * 128, bn = blockIdx.x * 128;
    const int nc = Kd >> 6;

    float acc[2][4][4];
#pragma unroll
    for (int i = 0; i < 2; i++)
#pragma unroll
        for (int j = 0; j < 4; j++)
#pragma unroll
            for (int q = 0; q < 4; q++) acc[i][j][q] = 0.f;

    auto load_chunk = [&](int ch, int stg) {
        uint32_t st = ab + stg * STAGE_SZ;
        int k0 = ch * 64;
#pragma unroll
        for (int c = tid; c < 1024; c += 512) {
            int r = c >> 3, cc = c & 7;
            uint32_t sw = swz((uint32_t)(r * 128 + cc * 16));
            size_t ga = (size_t)(bm + r) * Kd + k0 + cc * 8;
            cp16(st + S_AH + sw, Ahi + ga);
            cp16(st + S_AL + sw, Alo + ga);
            size_t gb = (size_t)(bn + r) * Kd + k0 + cc * 8;
            cp16(st + S_BH + sw, Bhi + gb);
            cp16(st + S_BL + sw, Blo + gb);
        }
    };

    load_chunk(0, 0); CP_COMMIT();
    load_chunk(1, 1); CP_COMMIT();
    for (int ch = 0; ch < nc; ch++) {
        if (ch == nc - 1) { CP_WAIT(0); } else { CP_WAIT(1); }
        __syncthreads();
        int stg = ch % 3;
        compute_chunk(ab + stg * STAGE_SZ, warp_m, warp_n, lane, acc);
        if (ch + 2 < nc) {
            load_chunk(ch + 2, (ch + 2) % 3);
            CP_COMMIT();
        }
    }

    // ---- epilogue ----
    const int tgm = lane >> 2;
    const int tgn = (lane & 3) * 2;
#pragma unroll
    for (int mt = 0; mt < 2; mt++) {
#pragma unroll
        for (int dh = 0; dh < 2; dh++) {
            int m = bm + warp_m * 32 + mt * 16 + tgm + dh * 8;
            float ya = 0.f, da = 0.f;
            if (ADD_YD) { ya = __ldg(yv + m); da = __ldg(dv + m); }
#pragma unroll
            for (int nt = 0; nt < 4; nt++) {
                int n = bn + warp_n * 32 + nt * 8 + tgn;
                float v0 = acc[mt][nt][dh * 2 + 0];
                float v1 = acc[mt][nt][dh * 2 + 1];
                float2 bb = *(const float2*)(bias + n);
                v0 += bb.x; v1 += bb.y;
                if (ADD_YD) {
                    float2 w0 = *(const float2*)(wyd + n);
                    float2 w1 = *(const float2*)(wyd + N + n);
                    v0 += ya * w0.x + da * w1.x;
                    v1 += ya * w0.y + da * w1.y;
                }
                v0 = elu_f(v0); v1 = elu_f(v1);
                if (OUT_F32) {
                    *(float2*)(outF + (size_t)m * N + n) = make_float2(v0, v1);
                } else {
                    __nv_bfloat16 h0 = __float2bfloat16(v0);
                    __nv_bfloat16 h1 = __float2bfloat16(v1);
                    __nv_bfloat162 hp; hp.x = h0; hp.y = h1;
                    __nv_bfloat162 lp;
                    lp.x = __float2bfloat16(v0 - __bfloat162float(h0));
                    lp.y = __float2bfloat16(v1 - __bfloat162float(h1));
                    *(__nv_bfloat162*)(outHi + (size_t)m * N + n) = hp;
                    *(__nv_bfloat162*)(outLo + (size_t)m * N + n) = lp;
                }
            }
        }
    }
}

// ========================= z head: gathered grouped GEMM =========================
__global__ void __launch_bounds__(512, 1)
zheadmma(const __nv_bfloat16* __restrict__ Ahi, const __nv_bfloat16* __restrict__ Alo,
         const __nv_bfloat16* __restrict__ Whi, const __nv_bfloat16* __restrict__ Wlo,
         const float* __restrict__ zhb, float* __restrict__ out)
{
    const int grp = blockIdx.z;
    const int cnt = g_cnt[grp];
    const int m0 = blockIdx.y * 128;
    if (m0 >= cnt) return;
    const int base = g_off[grp];
    const int bn = blockIdx.x * 128;

    extern __shared__ char smraw[];
    uint32_t sb = smem_u32(smraw);
    uint32_t ab = (sb + 1023u) & ~1023u;
    char* sm = smraw + (ab - sb);
    int* srow = (int*)(sm + 3 * STAGE_SZ);

    const int tid = threadIdx.x;
    const int wid = tid >> 5;
    const int lane = tid & 31;
    const int warp_m = wid & 3;
    const int warp_n = wid >> 2;

    if (tid < 128) {
        int mi = m0 + tid;
        srow[tid] = (mi < cnt) ? g_ridx[base + mi] : -1;
    }
    __syncthreads();
    const int safe0 = srow[0];

    const __nv_bfloat16* Wg_hi = Whi + (size_t)grp * 512 * 1024;
    const __nv_bfloat16* Wg_lo = Wlo + (size_t)grp * 512 * 1024;

    float acc[2][4][4];
#pragma unroll
    for (int i = 0; i < 2; i++)
#pragma unroll
        for (int j = 0; j < 4; j++)
#pragma unroll
            for (int q = 0; q < 4; q++) acc[i][j][q] = 0.f;

    auto load_chunk = [&](int ch, int stg) {
        uint32_t st = ab + stg * STAGE_SZ;
        int k0 = ch * 64;
#pragma unroll
        for (int c = tid; c < 1024; c += 512) {
            int r = c >> 3, cc = c & 7;
            uint32_t sw = swz((uint32_t)(r * 128 + cc * 16));
            int gr = srow[r]; if (gr < 0) gr = safe0;
            size_t ga = (size_t)gr * 1024 + k0 + cc * 8;
            cp16(st + S_AH + sw, Ahi + ga);
            cp16(st + S_AL + sw, Alo + ga);
            size_t gb = (size_t)(bn + r) * 1024 + k0 + cc * 8;
            cp16(st + S_BH + sw, Wg_hi + gb);
            cp16(st + S_BL + sw, Wg_lo + gb);
        }
    };

    load_chunk(0, 0); CP_COMMIT();
    load_chunk(1, 1); CP_COMMIT();
    for (int ch = 0; ch < 16; ch++) {
        if (ch == 15) { CP_WAIT(0); } else { CP_WAIT(1); }
        __syncthreads();
        int stg = ch % 3;
        compute_chunk(ab + stg * STAGE_SZ, warp_m, warp_n, lane, acc);
        if (ch + 2 < 16) {
            load_chunk(ch + 2, (ch + 2) % 3);
            CP_COMMIT();
        }
    }

    const int tgm = lane >> 2;
    const int tgn = (lane & 3) * 2;
#pragma unroll
    for (int mt = 0; mt < 2; mt++) {
#pragma unroll
        for (int dh = 0; dh < 2; dh++) {
            int mloc = warp_m * 32 + mt * 16 + tgm + dh * 8;
            int rg = srow[mloc];
            if (rg < 0) continue;
            float* op = out + (size_t)rg * OUTC + 11;
#pragma unroll
            for (int nt = 0; nt < 4; nt++) {
                int n = bn + warp_n * 32 + nt * 8 + tgn;
                float v0 = acc[mt][nt][dh * 2 + 0] + __ldg(zhb + grp * 512 + n);
                float v1 = acc[mt][nt][dh * 2 + 1] + __ldg(zhb + grp * 512 + n + 1);
                if (n < 256) {
                    v0 = fminf(fmaxf(v0, -100.f), 100.f);
                    v1 = fminf(fmaxf(v1, -100.f), 100.f);
                } else {
                    v0 = fminf(softplus_f(v0) + 0.001f, 100.f);
                    v1 = fminf(softplus_f(v1) + 0.001f, 100.f);
                }
                op[n] = v0;
                op[n + 1] = v1;
            }
        }
    }
}

// ========================= small head kernels (fp32) =========================
__global__ void thead_kernel(const float* __restrict__ hid, const float* __restrict__ tw2,
                             const float* __restrict__ tb2, float* __restrict__ out)
{
    int w = (blockIdx.x * blockDim.x + threadIdx.x) >> 5;
    int lane = threadIdx.x & 31;
    if (w >= BATCH) return;
    const float* hr = hid + (size_t)w * 256;
    float acc[7] = {0.f, 0.f, 0.f, 0.f, 0.f, 0.f, 0.f};
    for (int k = lane; k < 256; k += 32) {
        float h = hr[k];
        const float* wr = tw2 + k * 7;
#pragma unroll
        for (int j = 0; j < 7; j++) acc[j] = fmaf(h, wr[j], acc[j]);
    }
#pragma unroll
    for (int j = 0; j < 7; j++)
        for (int o = 16; o > 0; o >>= 1) acc[j] += __shfl_xor_sync(0xffffffffu, acc[j], o);
    if (lane == 0) {
#pragma unroll
        for (int j = 0; j < 7; j++) {
            float v = elu_f(acc[j] + tb2[j]);
            out[(size_t)w * OUTC + j] = fminf(fmaxf(v, -10.f), 10.f);
        }
    }
}
__global__ void head2_kernel(const float* __restrict__ hid, const int* __restrict__ t,
                             const float* __restrict__ hW, const float* __restrict__ hb,
                             float* __restrict__ out, int col0)
{
    int w = (blockIdx.x * blockDim.x + threadIdx.x) >> 5;
    int lane = threadIdx.x & 31;
    if (w >= BATCH) return;
    int tt = t[w];
    const float*  hr = hid + (size_t)w * 1024;
    const float2* wp = (const float2*)(hW + (size_t)tt * 2048);
    float a0 = 0.f, a1 = 0.f;
    for (int k = lane; k < 1024; k += 32) {
        float h = hr[k];
        float2 ww = wp[k];
        a0 = fmaf(h, ww.x, a0);
        a1 = fmaf(h, ww.y, a1);
    }
    for (int o = 16; o > 0; o >>= 1) {
        a0 += __shfl_xor_sync(0xffffffffu, a0, o);
        a1 += __shfl_xor_sync(0xffffffffu, a1, o);
    }
    if (lane == 0) {
        float loc = fminf(fmaxf(a0 + hb[tt * 2 + 0], -1e6f), 1e6f);
        float sc  = fminf(softplus_f(a1 + hb[tt * 2 + 1]) + 1e-3f, 1e6f);
        out[(size_t)w * OUTC + col0]     = loc;
        out[(size_t)w * OUTC + col0 + 1] = sc;
    }
}

// ========================= launch =========================
extern "C" void kernel_launch(void* const* d_in, const int* in_sizes, int n_in,
                              void* d_out, int out_size)
{
    const float* x   = (const float*)d_in[0];
    const int*   t   = (const int*)  d_in[1];
    const float* yv  = (const float*)d_in[2];
    const float* dv  = (const float*)d_in[3];
    const float* tw0 = (const float*)d_in[4];
    const float* tb0 = (const float*)d_in[5];
    const float* tw1 = (const float*)d_in[6];
    const float* tb1 = (const float*)d_in[7];
    const float* tw2 = (const float*)d_in[8];
    const float* tb2 = (const float*)d_in[9];
    const float* yw0 = (const float*)d_in[10];
    const float* yb0 = (const float*)d_in[11];
    const float* yw1 = (const float*)d_in[12];
    const float* yb1 = (const float*)d_in[13];
    const float* yhW = (const float*)d_in[14];
    const float* yhb = (const float*)d_in[15];
    const float* dw0 = (const float*)d_in[16];
    const float* db0 = (const float*)d_in[17];
    const float* dw1 = (const float*)d_in[18];
    const float* db1 = (const float*)d_in[19];
    const float* dhW = (const float*)d_in[20];
    const float* dhb = (const float*)d_in[21];
    const float* zw0 = (const float*)d_in[22];
    const float* zb0 = (const float*)d_in[23];
    const float* zw1 = (const float*)d_in[24];
    const float* zb1 = (const float*)d_in[25];
    const float* zhW = (const float*)d_in[26];
    const float* zhb = (const float*)d_in[27];
    float* out = (float*)d_out;

    __nv_bfloat16 *xhi, *xlo, *a1hi, *a1lo, *a2hi, *a2lo, *whi, *wlo;
    float* f32buf;
    cudaGetSymbolAddress((void**)&xhi, g_xhi);
    cudaGetSymbolAddress((void**)&xlo, g_xlo);
    cudaGetSymbolAddress((void**)&a1hi, g_a1hi);
    cudaGetSymbolAddress((void**)&a1lo, g_a1lo);
    cudaGetSymbolAddress((void**)&a2hi, g_a2hi);
    cudaGetSymbolAddress((void**)&a2lo, g_a2lo);
    cudaGetSymbolAddress((void**)&whi, g_whi);
    cudaGetSymbolAddress((void**)&wlo, g_wlo);
    cudaGetSymbolAddress((void**)&f32buf, g_f32);

    cudaFuncSetAttribute((const void*)gemm3bf<false, false>, cudaFuncAttributeMaxDynamicSharedMemorySize, SMEM_REQ);
    cudaFuncSetAttribute((const void*)gemm3bf<false, true>,  cudaFuncAttributeMaxDynamicSharedMemorySize, SMEM_REQ);
    cudaFuncSetAttribute((const void*)gemm3bf<true, false>,  cudaFuncAttributeMaxDynamicSharedMemorySize, SMEM_REQ);
    cudaFuncSetAttribute((const void*)zheadmma,               cudaFuncAttributeMaxDynamicSharedMemorySize, SMEM_REQ);

    // ---- bucketing by t ----
    k_init<<<1, 32>>>();
    k_hist<<<(BATCH + 255) / 256, 256>>>(t);
    k_off<<<1, 32>>>();
    k_scatter<<<(BATCH + 255) / 256, 256>>>(t);

    // ---- preprocessing: split x, transpose+split weights ----
    {
        int n = BATCH * 1024;
        xsplit_kernel<<<(n + 255) / 256, 256>>>(x, xhi, xlo, n);
        dim3 tb(32, 8);
        wsplit_kernel<<<dim3(256 / 32, 1024 / 32), tb>>>(tw0, whi + OFF_TW0, wlo + OFF_TW0, 1024, 256);
        wsplit_kernel<<<dim3(256 / 32, 256 / 32),  tb>>>(tw1, whi + OFF_TW1, wlo + OFF_TW1, 256, 256);
        Ptr6 tab;
        tab.p[0] = yw0;            tab.off[0] = OFF_YW0;
        tab.p[1] = yw1;            tab.off[1] = OFF_YW1;
        tab.p[2] = dw0;            tab.off[2] = OFF_DW0;
        tab.p[3] = dw1;            tab.off[3] = OFF_DW1;
        tab.p[4] = zw0 + 2 * 1024; tab.off[4] = OFF_ZW0;
        tab.p[5] = zw1;            tab.off[5] = OFF_ZW1;
        wsplit6_kernel<<<dim3(32, 32, 6), tb>>>(tab, whi, wlo);
        wsplitz_kernel<<<dim3(16, 32, 7), tb>>>(zhW, whi, wlo);
    }

    const dim3 blk(512);
    const dim3 g1024(8, 128);
    const dim3 g256(2, 128);
    const int headBlocks = (BATCH * 32) / 256;

    // ---- t path ----
    gemm3bf<false, false><<<g256, blk, SMEM_REQ>>>(xhi, xlo, whi + OFF_TW0, wlo + OFF_TW0, tb0,
        256, 1024, nullptr, a1hi, a1lo, nullptr, nullptr, nullptr);
    gemm3bf<false, true><<<g256, blk, SMEM_REQ>>>(a1hi, a1lo, whi + OFF_TW1, wlo + OFF_TW1, tb1,
        256, 256, f32buf, nullptr, nullptr, nullptr, nullptr, nullptr);
    thead_kernel<<<headBlocks, 256>>>(f32buf, tw2, tb2, out);

    // ---- y path ----
    gemm3bf<false, false><<<g1024, blk, SMEM_REQ>>>(xhi, xlo, whi + OFF_YW0, wlo + OFF_YW0, yb0,
        1024, 1024, nullptr, a1hi, a1lo, nullptr, nullptr, nullptr);
    gemm3bf<false, true><<<g1024, blk, SMEM_REQ>>>(a1hi, a1lo, whi + OFF_YW1, wlo + OFF_YW1, yb1,
        1024, 1024, f32buf, nullptr, nullptr, nullptr, nullptr, nullptr);
    head2_kernel<<<headBlocks, 256>>>(f32buf, t, yhW, yhb, out, 7);

    // ---- d path ----
    gemm3bf<false, false><<<g1024, blk, SMEM_REQ>>>(xhi, xlo, whi + OFF_DW0, wlo + OFF_DW0, db0,
        1024, 1024, nullptr, a1hi, a1lo, nullptr, nullptr, nullptr);
    gemm3bf<false, true><<<g1024, blk, SMEM_REQ>>>(a1hi, a1lo, whi + OFF_DW1, wlo + OFF_DW1, db1,
        1024, 1024, f32buf, nullptr, nullptr, nullptr, nullptr, nullptr);
    head2_kernel<<<headBlocks, 256>>>(f32buf, t, dhW, dhb, out, 9);

    // ---- z path (cat([y,d,x]) folded into epilogue rank-2 update) ----
    gemm3bf<true, false><<<g1024, blk, SMEM_REQ>>>(xhi, xlo, whi + OFF_ZW0, wlo + OFF_ZW0, zb0,
        1024, 1024, nullptr, a1hi, a1lo, yv, dv, zw0);
    gemm3bf<false, false><<<g1024, blk, SMEM_REQ>>>(a1hi, a1lo, whi + OFF_ZW1, wlo + OFF_ZW1, zb1,
        1024, 1024, nullptr, a2hi, a2lo, nullptr, nullptr, nullptr);
    zheadmma<<<dim3(4, 128, 7), blk, SMEM_REQ>>>(a2hi, a2lo,
        whi + OFF_ZHW, wlo + OFF_ZHW, zhb, out);
}

// round 5
// speedup vs baseline: 3.4098x; 1.0774x over previous
#include <cuda_runtime.h>
#include <cuda_bf16.h>
#include <cstdint>
#include <math.h>

#define BATCH 16384
#define OUTC  523   // 7 + 4 + 512

// ========================= PTX helpers (sm_80-level only) =========================
__device__ __forceinline__ uint32_t smem_u32(const void* p) {
    uint32_t a;
    asm("{ .reg .u64 t; cvta.to.shared.u64 t, %1; cvt.u32.u64 %0, t; }" : "=r"(a) : "l"(p));
    return a;
}
__device__ __forceinline__ void cp16(uint32_t saddr, const void* g) {
    asm volatile("cp.async.cg.shared.global [%0], [%1], 16;" :: "r"(saddr), "l"(g));
}
#define CP_COMMIT() asm volatile("cp.async.commit_group;" ::: "memory")
#define CP_WAIT(n)  asm volatile("cp.async.wait_group %0;" :: "n"(n) : "memory")

__device__ __forceinline__ void ldmx4(uint32_t& r0, uint32_t& r1, uint32_t& r2, uint32_t& r3, uint32_t addr) {
    asm volatile("ldmatrix.sync.aligned.m8n8.x4.shared.b16 {%0,%1,%2,%3}, [%4];"
                 : "=r"(r0), "=r"(r1), "=r"(r2), "=r"(r3) : "r"(addr));
}
__device__ __forceinline__ void mma16816(float* c, const uint32_t* a, uint32_t b0, uint32_t b1) {
    asm volatile("mma.sync.aligned.m16n8k16.row.col.f32.bf16.bf16.f32 "
                 "{%0,%1,%2,%3}, {%4,%5,%6,%7}, {%8,%9}, {%0,%1,%2,%3};"
                 : "+f"(c[0]), "+f"(c[1]), "+f"(c[2]), "+f"(c[3])
                 : "r"(a[0]), "r"(a[1]), "r"(a[2]), "r"(a[3]), "r"(b0), "r"(b1));
}
__device__ __forceinline__ uint32_t swz(uint32_t off) { return off ^ ((off >> 3) & 0x70); }

// ========================= scratch (per-path, concurrent-safe) =========================
__device__ __nv_bfloat16 g_xhi[BATCH * 1024];
__device__ __nv_bfloat16 g_xlo[BATCH * 1024];
__device__ __nv_bfloat16 g_y1hi[BATCH * 1024];
__device__ __nv_bfloat16 g_y1lo[BATCH * 1024];
__device__ __nv_bfloat16 g_d1hi[BATCH * 1024];
__device__ __nv_bfloat16 g_d1lo[BATCH * 1024];
__device__ __nv_bfloat16 g_z1hi[BATCH * 1024];
__device__ __nv_bfloat16 g_z1lo[BATCH * 1024];
__device__ __nv_bfloat16 g_z2hi[BATCH * 1024];
__device__ __nv_bfloat16 g_z2lo[BATCH * 1024];
__device__ __nv_bfloat16 g_t1hi[BATCH * 256];
__device__ __nv_bfloat16 g_t1lo[BATCH * 256];
__device__ float         g_fy[BATCH * 1024];
__device__ float         g_fd[BATCH * 1024];
__device__ float         g_ft[BATCH * 256];
__device__ __nv_bfloat16 g_whi[10300000];
__device__ __nv_bfloat16 g_wlo[10300000];
__device__ int g_ridx[BATCH];
__device__ int g_cnt[8];
__device__ int g_off[8];
__device__ int g_cur[8];

// weight-pool offsets (elements)
#define OFF_TW0 0
#define OFF_TW1 262144
#define OFF_YW0 327680
#define OFF_YW1 1376256
#define OFF_DW0 2424832
#define OFF_DW1 3473408
#define OFF_ZW0 4521984
#define OFF_ZW1 5570560
#define OFF_ZHW 6619136   // + t*524288

__device__ __forceinline__ float elu_f(float v) { return v > 0.f ? v : expm1f(v); }
__device__ __forceinline__ float softplus_f(float v) {
    return fmaxf(v, 0.f) + log1pf(expf(-fabsf(v)));
}

// ========================= preprocessing =========================
__global__ void xsplit_kernel(const float* __restrict__ x, __nv_bfloat16* __restrict__ hi,
                              __nv_bfloat16* __restrict__ lo, int n) {
    int i = blockIdx.x * blockDim.x + threadIdx.x;
    if (i < n) {
        float v = x[i];
        __nv_bfloat16 h = __float2bfloat16(v);
        hi[i] = h;
        lo[i] = __float2bfloat16(v - __bfloat162float(h));
    }
}
struct WEnt { const float* p; unsigned long long off; int kd, n; };
struct WTab { WEnt e[15]; };
// transpose + split ALL weight matrices in one launch: W[kd,n] fp32 -> Wt[n,kd] hi/lo bf16
__global__ void wsplit_all(WTab tab, __nv_bfloat16* __restrict__ hi, __nv_bfloat16* __restrict__ lo) {
    WEnt E = tab.e[blockIdx.z];
    int n0 = blockIdx.x * 32, k0 = blockIdx.y * 32;
    if (n0 >= E.n || k0 >= E.kd) return;
    __shared__ float tile[32][33];
    int tx = threadIdx.x, ty = threadIdx.y; // 32 x 8
    for (int i = ty; i < 32; i += 8)
        tile[i][tx] = E.p[(size_t)(k0 + i) * E.n + n0 + tx];
    __syncthreads();
    __nv_bfloat16* H = hi + E.off;
    __nv_bfloat16* L = lo + E.off;
    for (int i = ty; i < 32; i += 8) {
        float v = tile[tx][i];  // = W[k0+tx][n0+i]
        size_t o = (size_t)(n0 + i) * E.kd + k0 + tx;
        __nv_bfloat16 h = __float2bfloat16(v);
        H[o] = h;
        L[o] = __float2bfloat16(v - __bfloat162float(h));
    }
}

// ========================= bucketing by t =========================
__global__ void k_init() { if (threadIdx.x < 8) g_cnt[threadIdx.x] = 0; }
__global__ void k_hist(const int* __restrict__ t) {
    int i = blockIdx.x * blockDim.x + threadIdx.x;
    if (i < BATCH) atomicAdd(&g_cnt[t[i]], 1);
}
__global__ void k_off() {
    if (threadIdx.x == 0) {
        int s = 0;
        for (int i = 0; i < 7; i++) { g_off[i] = s; g_cur[i] = s; s += g_cnt[i]; }
    }
}
__global__ void k_scatter(const int* __restrict__ t) {
    int i = blockIdx.x * blockDim.x + threadIdx.x;
    if (i < BATCH) { int p = atomicAdd(&g_cur[t[i]], 1); g_ridx[p] = i; }
}

// ========================= 3xBF16 mma.sync GEMM =========================
// CTA tile 256x128, K-chunk 64, 512 threads = 16 warps, warp tile 64x32,
// 2-stage cp.async pipeline, one __syncthreads per chunk.
#define S_AH 0
#define S_AL 32768
#define S_BH 65536
#define S_BL 81920
#define STAGE_SZ 98304
#define SMEM_REQ 199680

__device__ __forceinline__ void compute_chunk(uint32_t st, int warp_m, int warp_n, int lane,
                                              float acc[4][4][4])
{
    const int lrow = lane & 7;
    const int lmat = lane >> 3;
#pragma unroll
    for (int ks = 0; ks < 4; ks++) {
        uint32_t bh[8], bl[8];
#pragma unroll
        for (int p = 0; p < 2; p++) {
            int ntile = p * 2 + (lmat >> 1);
            int half = lmat & 1;
            uint32_t off = (uint32_t)((warp_n * 32 + ntile * 8 + lrow) * 128 + (ks * 16 + half * 8) * 2);
            uint32_t a = swz(off);
            ldmx4(bh[p * 4 + 0], bh[p * 4 + 1], bh[p * 4 + 2], bh[p * 4 + 3], st + S_BH + a);
            ldmx4(bl[p * 4 + 0], bl[p * 4 + 1], bl[p * 4 + 2], bl[p * 4 + 3], st + S_BL + a);
        }
#pragma unroll
        for (int mt = 0; mt < 4; mt++) {
            uint32_t ah[4], al[4];
            uint32_t off = (uint32_t)((warp_m * 64 + mt * 16 + (lmat & 1) * 8 + lrow) * 128
                                      + (ks * 16 + (lmat >> 1) * 8) * 2);
            uint32_t a = swz(off);
            ldmx4(ah[0], ah[1], ah[2], ah[3], st + S_AH + a);
            ldmx4(al[0], al[1], al[2], al[3], st + S_AL + a);
#pragma unroll
            for (int nt = 0; nt < 4; nt++) {
                mma16816(acc[mt][nt], ah, bh[nt * 2], bh[nt * 2 + 1]);
                mma16816(acc[mt][nt], ah, bl[nt * 2], bl[nt * 2 + 1]);
                mma16816(acc[mt][nt], al, bh[nt * 2], bh[nt * 2 + 1]);
            }
        }
    }
}

template<bool ADD_YD, bool OUT_F32>
__global__ void __launch_bounds__(512, 1)
gemm3bf(const __nv_bfloat16* __restrict__ Ahi, const __nv_bfloat16* __restrict__ Alo,
        const __nv_bfloat16* __restrict__ Bhi, const __nv_bfloat16* __restrict__ Blo,
        const float* __restrict__ bias, int N, int Kd,
        float* __restrict__ outF, __nv_bfloat16* __restrict__ outHi, __nv_bfloat16* __restrict__ outLo,
        const float* __restrict__ yv, const float* __restrict__ dv, const float* __restrict__ wyd)
{
    extern __shared__ char smraw[];
    uint32_t sb = smem_u32(smraw);
    uint32_t ab = (sb + 1023u) & ~1023u;

    const int tid = threadIdx.x;
    const int wid = tid >> 5;
    const int lane = tid & 31;
    const int warp_m = wid & 3;
    const int warp_n = wid >> 2;
    const int bm = blockIdx.y * 256, bn = blockIdx.x * 128;
    const int nc = Kd >> 6;

    float acc[4][4][4];
#pragma unroll
    for (int i = 0; i < 4; i++)
#pragma unroll
        for (int j = 0; j < 4; j++)
#pragma unroll
            for (int q = 0; q < 4; q++) acc[i][j][q] = 0.f;

    auto load_chunk = [&](int ch, int stg) {
        uint32_t st = ab + stg * STAGE_SZ;
        int k0 = ch * 64;
#pragma unroll
        for (int c = tid; c < 2048; c += 512) {
            int r = c >> 3, cc = c & 7;
            uint32_t sw = swz((uint32_t)(r * 128 + cc * 16));
            size_t ga = (size_t)(bm + r) * Kd + k0 + cc * 8;
            cp16(st + S_AH + sw, Ahi + ga);
            cp16(st + S_AL + sw, Alo + ga);
        }
#pragma unroll
        for (int c = tid; c < 1024; c += 512) {
            int r = c >> 3, cc = c & 7;
            uint32_t sw = swz((uint32_t)(r * 128 + cc * 16));
            size_t gb = (size_t)(bn + r) * Kd + k0 + cc * 8;
            cp16(st + S_BH + sw, Bhi + gb);
            cp16(st + S_BL + sw, Blo + gb);
        }
    };

    load_chunk(0, 0); CP_COMMIT();
    for (int ch = 0; ch < nc; ch++) {
        CP_WAIT(0);
        __syncthreads();
        if (ch + 1 < nc) { load_chunk(ch + 1, (ch + 1) & 1); CP_COMMIT(); }
        compute_chunk(ab + (ch & 1) * STAGE_SZ, warp_m, warp_n, lane, acc);
    }

    // ---- epilogue ----
    const int tgm = lane >> 2;
    const int tgn = (lane & 3) * 2;
#pragma unroll
    for (int mt = 0; mt < 4; mt++) {
#pragma unroll
        for (int dh = 0; dh < 2; dh++) {
            int m = bm + warp_m * 64 + mt * 16 + tgm + dh * 8;
            float ya = 0.f, da = 0.f;
            if (ADD_YD) { ya = __ldg(yv + m); da = __ldg(dv + m); }
#pragma unroll
            for (int nt = 0; nt < 4; nt++) {
                int n = bn + warp_n * 32 + nt * 8 + tgn;
                float v0 = acc[mt][nt][dh * 2 + 0];
                float v1 = acc[mt][nt][dh * 2 + 1];
                float2 bb = *(const float2*)(bias + n);
                v0 += bb.x; v1 += bb.y;
                if (ADD_YD) {
                    float2 w0 = *(const float2*)(wyd + n);
                    float2 w1 = *(const float2*)(wyd + N + n);
                    v0 += ya * w0.x + da * w1.x;
                    v1 += ya * w0.y + da * w1.y;
                }
                v0 = elu_f(v0); v1 = elu_f(v1);
                if (OUT_F32) {
                    *(float2*)(outF + (size_t)m * N + n) = make_float2(v0, v1);
                } else {
                    __nv_bfloat16 h0 = __float2bfloat16(v0);
                    __nv_bfloat16 h1 = __float2bfloat16(v1);
                    __nv_bfloat162 hp; hp.x = h0; hp.y = h1;
                    __nv_bfloat162 lp;
                    lp.x = __float2bfloat16(v0 - __bfloat162float(h0));
                    lp.y = __float2bfloat16(v1 - __bfloat162float(h1));
                    *(__nv_bfloat162*)(outHi + (size_t)m * N + n) = hp;
                    *(__nv_bfloat162*)(outLo + (size_t)m * N + n) = lp;
                }
            }
        }
    }
}

// ========================= z head: gathered grouped GEMM =========================
__global__ void __launch_bounds__(512, 1)
zheadmma(const __nv_bfloat16* __restrict__ Ahi, const __nv_bfloat16* __restrict__ Alo,
         const __nv_bfloat16* __restrict__ Whi, const __nv_bfloat16* __restrict__ Wlo,
         const float* __restrict__ zhb, float* __restrict__ out)
{
    const int grp = blockIdx.z;
    const int cnt = g_cnt[grp];
    const int m0 = blockIdx.y * 256;
    if (m0 >= cnt) return;
    const int base = g_off[grp];
    const int bn = blockIdx.x * 128;

    extern __shared__ char smraw[];
    uint32_t sb = smem_u32(smraw);
    uint32_t ab = (sb + 1023u) & ~1023u;
    char* sm = smraw + (ab - sb);
    int* srow = (int*)(sm + 2 * STAGE_SZ);

    const int tid = threadIdx.x;
    const int wid = tid >> 5;
    const int lane = tid & 31;
    const int warp_m = wid & 3;
    const int warp_n = wid >> 2;

    if (tid < 256) {
        int mi = m0 + tid;
        srow[tid] = (mi < cnt) ? g_ridx[base + mi] : -1;
    }
    __syncthreads();
    const int safe0 = srow[0];

    const __nv_bfloat16* Wg_hi = Whi + (size_t)grp * 512 * 1024;
    const __nv_bfloat16* Wg_lo = Wlo + (size_t)grp * 512 * 1024;

    float acc[4][4][4];
#pragma unroll
    for (int i = 0; i < 4; i++)
#pragma unroll
        for (int j = 0; j < 4; j++)
#pragma unroll
            for (int q = 0; q < 4; q++) acc[i][j][q] = 0.f;

    auto load_chunk = [&](int ch, int stg) {
        uint32_t st = ab + stg * STAGE_SZ;
        int k0 = ch * 64;
#pragma unroll
        for (int c = tid; c < 2048; c += 512) {
            int r = c >> 3, cc = c & 7;
            uint32_t sw = swz((uint32_t)(r * 128 + cc * 16));
            int gr = srow[r]; if (gr < 0) gr = safe0;
            size_t ga = (size_t)gr * 1024 + k0 + cc * 8;
            cp16(st + S_AH + sw, Ahi + ga);
            cp16(st + S_AL + sw, Alo + ga);
        }
#pragma unroll
        for (int c = tid; c < 1024; c += 512) {
            int r = c >> 3, cc = c & 7;
            uint32_t sw = swz((uint32_t)(r * 128 + cc * 16));
            size_t gb = (size_t)(bn + r) * 1024 + k0 + cc * 8;
            cp16(st + S_BH + sw, Wg_hi + gb);
            cp16(st + S_BL + sw, Wg_lo + gb);
        }
    };

    load_chunk(0, 0); CP_COMMIT();
    for (int ch = 0; ch < 16; ch++) {
        CP_WAIT(0);
        __syncthreads();
        if (ch + 1 < 16) { load_chunk(ch + 1, (ch + 1) & 1); CP_COMMIT(); }
        compute_chunk(ab + (ch & 1) * STAGE_SZ, warp_m, warp_n, lane, acc);
    }

    const int tgm = lane >> 2;
    const int tgn = (lane & 3) * 2;
#pragma unroll
    for (int mt = 0; mt < 4; mt++) {
#pragma unroll
        for (int dh = 0; dh < 2; dh++) {
            int mloc = warp_m * 64 + mt * 16 + tgm + dh * 8;
            int rg = srow[mloc];
            if (rg < 0) continue;
            float* op = out + (size_t)rg * OUTC + 11;
#pragma unroll
            for (int nt = 0; nt < 4; nt++) {
                int n = bn + warp_n * 32 + nt * 8 + tgn;
                float v0 = acc[mt][nt][dh * 2 + 0] + __ldg(zhb + grp * 512 + n);
                float v1 = acc[mt][nt][dh * 2 + 1] + __ldg(zhb + grp * 512 + n + 1);
                if (n < 256) {
                    v0 = fminf(fmaxf(v0, -100.f), 100.f);
                    v1 = fminf(fmaxf(v1, -100.f), 100.f);
                } else {
                    v0 = fminf(softplus_f(v0) + 0.001f, 100.f);
                    v1 = fminf(softplus_f(v1) + 0.001f, 100.f);
                }
                op[n] = v0;
                op[n + 1] = v1;
            }
        }
    }
}

// ========================= small head kernels (fp32) =========================
__global__ void thead_kernel(const float* __restrict__ hid, const float* __restrict__ tw2,
                             const float* __restrict__ tb2, float* __restrict__ out)
{
    int w = (blockIdx.x * blockDim.x + threadIdx.x) >> 5;
    int lane = threadIdx.x & 31;
    if (w >= BATCH) return;
    const float* hr = hid + (size_t)w * 256;
    float acc[7] = {0.f, 0.f, 0.f, 0.f, 0.f, 0.f, 0.f};
    for (int k = lane; k < 256; k += 32) {
        float h = hr[k];
        const float* wr = tw2 + k * 7;
#pragma unroll
        for (int j = 0; j < 7; j++) acc[j] = fmaf(h, wr[j], acc[j]);
    }
#pragma unroll
    for (int j = 0; j < 7; j++)
        for (int o = 16; o > 0; o >>= 1) acc[j] += __shfl_xor_sync(0xffffffffu, acc[j], o);
    if (lane == 0) {
#pragma unroll
        for (int j = 0; j < 7; j++) {
            float v = elu_f(acc[j] + tb2[j]);
            out[(size_t)w * OUTC + j] = fminf(fmaxf(v, -10.f), 10.f);
        }
    }
}
__global__ void head2_kernel(const float* __restrict__ hid, const int* __restrict__ t,
                             const float* __restrict__ hW, const float* __restrict__ hb,
                             float* __restrict__ out, int col0)
{
    int w = (blockIdx.x * blockDim.x + threadIdx.x) >> 5;
    int lane = threadIdx.x & 31;
    if (w >= BATCH) return;
    int tt = t[w];
    const float*  hr = hid + (size_t)w * 1024;
    const float2* wp = (const float2*)(hW + (size_t)tt * 2048);
    float a0 = 0.f, a1 = 0.f;
    for (int k = lane; k < 1024; k += 32) {
        float h = hr[k];
        float2 ww = wp[k];
        a0 = fmaf(h, ww.x, a0);
        a1 = fmaf(h, ww.y, a1);
    }
    for (int o = 16; o > 0; o >>= 1) {
        a0 += __shfl_xor_sync(0xffffffffu, a0, o);
        a1 += __shfl_xor_sync(0xffffffffu, a1, o);
    }
    if (lane == 0) {
        float loc = fminf(fmaxf(a0 + hb[tt * 2 + 0], -1e6f), 1e6f);
        float sc  = fminf(softplus_f(a1 + hb[tt * 2 + 1]) + 1e-3f, 1e6f);
        out[(size_t)w * OUTC + col0]     = loc;
        out[(size_t)w * OUTC + col0 + 1] = sc;
    }
}

// ========================= launch =========================
extern "C" void kernel_launch(void* const* d_in, const int* in_sizes, int n_in,
                              void* d_out, int out_size)
{
    const float* x   = (const float*)d_in[0];
    const int*   t   = (const int*)  d_in[1];
    const float* yv  = (const float*)d_in[2];
    const float* dv  = (const float*)d_in[3];
    const float* tw0 = (const float*)d_in[4];
    const float* tb0 = (const float*)d_in[5];
    const float* tw1 = (const float*)d_in[6];
    const float* tb1 = (const float*)d_in[7];
    const float* tw2 = (const float*)d_in[8];
    const float* tb2 = (const float*)d_in[9];
    const float* yw0 = (const float*)d_in[10];
    const float* yb0 = (const float*)d_in[11];
    const float* yw1 = (const float*)d_in[12];
    const float* yb1 = (const float*)d_in[13];
    const float* yhW = (const float*)d_in[14];
    const float* yhb = (const float*)d_in[15];
    const float* dw0 = (const float*)d_in[16];
    const float* db0 = (const float*)d_in[17];
    const float* dw1 = (const float*)d_in[18];
    const float* db1 = (const float*)d_in[19];
    const float* dhW = (const float*)d_in[20];
    const float* dhb = (const float*)d_in[21];
    const float* zw0 = (const float*)d_in[22];
    const float* zb0 = (const float*)d_in[23];
    const float* zw1 = (const float*)d_in[24];
    const float* zb1 = (const float*)d_in[25];
    const float* zhW = (const float*)d_in[26];
    const float* zhb = (const float*)d_in[27];
    float* out = (float*)d_out;

    __nv_bfloat16 *xhi, *xlo, *y1hi, *y1lo, *d1hi, *d1lo, *z1hi, *z1lo, *z2hi, *z2lo, *t1hi, *t1lo, *whi, *wlo;
    float *fy, *fd, *ft;
    cudaGetSymbolAddress((void**)&xhi, g_xhi);
    cudaGetSymbolAddress((void**)&xlo, g_xlo);
    cudaGetSymbolAddress((void**)&y1hi, g_y1hi);
    cudaGetSymbolAddress((void**)&y1lo, g_y1lo);
    cudaGetSymbolAddress((void**)&d1hi, g_d1hi);
    cudaGetSymbolAddress((void**)&d1lo, g_d1lo);
    cudaGetSymbolAddress((void**)&z1hi, g_z1hi);
    cudaGetSymbolAddress((void**)&z1lo, g_z1lo);
    cudaGetSymbolAddress((void**)&z2hi, g_z2hi);
    cudaGetSymbolAddress((void**)&z2lo, g_z2lo);
    cudaGetSymbolAddress((void**)&t1hi, g_t1hi);
    cudaGetSymbolAddress((void**)&t1lo, g_t1lo);
    cudaGetSymbolAddress((void**)&whi, g_whi);
    cudaGetSymbolAddress((void**)&wlo, g_wlo);
    cudaGetSymbolAddress((void**)&fy, g_fy);
    cudaGetSymbolAddress((void**)&fd, g_fd);
    cudaGetSymbolAddress((void**)&ft, g_ft);

    static cudaStream_t s1, s2, s3;
    static cudaEvent_t ePre, eBkt, eJ1, eJ2, eJ3;
    static bool init = false;
    if (!init) {
        cudaStreamCreateWithFlags(&s1, cudaStreamNonBlocking);
        cudaStreamCreateWithFlags(&s2, cudaStreamNonBlocking);
        cudaStreamCreateWithFlags(&s3, cudaStreamNonBlocking);
        cudaEventCreateWithFlags(&ePre, cudaEventDisableTiming);
        cudaEventCreateWithFlags(&eBkt, cudaEventDisableTiming);
        cudaEventCreateWithFlags(&eJ1, cudaEventDisableTiming);
        cudaEventCreateWithFlags(&eJ2, cudaEventDisableTiming);
        cudaEventCreateWithFlags(&eJ3, cudaEventDisableTiming);
        cudaFuncSetAttribute((const void*)gemm3bf<false, false>, cudaFuncAttributeMaxDynamicSharedMemorySize, SMEM_REQ);
        cudaFuncSetAttribute((const void*)gemm3bf<false, true>,  cudaFuncAttributeMaxDynamicSharedMemorySize, SMEM_REQ);
        cudaFuncSetAttribute((const void*)gemm3bf<true, false>,  cudaFuncAttributeMaxDynamicSharedMemorySize, SMEM_REQ);
        cudaFuncSetAttribute((const void*)zheadmma,               cudaFuncAttributeMaxDynamicSharedMemorySize, SMEM_REQ);
        init = true;
    }

    // ---- preprocessing on stream 0 (2 launches) ----
    xsplit_kernel<<<(BATCH * 1024 + 255) / 256, 256>>>(x, xhi, xlo, BATCH * 1024);
    WTab tab;
    tab.e[0]  = { tw0,            OFF_TW0, 1024, 256 };
    tab.e[1]  = { tw1,            OFF_TW1, 256,  256 };
    tab.e[2]  = { yw0,            OFF_YW0, 1024, 1024 };
    tab.e[3]  = { yw1,            OFF_YW1, 1024, 1024 };
    tab.e[4]  = { dw0,            OFF_DW0, 1024, 1024 };
    tab.e[5]  = { dw1,            OFF_DW1, 1024, 1024 };
    tab.e[6]  = { zw0 + 2 * 1024, OFF_ZW0, 1024, 1024 };
    tab.e[7]  = { zw1,            OFF_ZW1, 1024, 1024 };
    for (int g = 0; g < 7; g++)
        tab.e[8 + g] = { zhW + (size_t)g * 1024 * 512,
                         (unsigned long long)(OFF_ZHW + (size_t)g * 524288), 1024, 512 };
    wsplit_all<<<dim3(32, 32, 15), dim3(32, 8)>>>(tab, whi, wlo);
    cudaEventRecord(ePre, 0);

    const dim3 blk(512);
    const dim3 g1024(8, 64);   // N=1024, M blocks of 256
    const dim3 g256(2, 64);    // N=256
    const int headBlocks = (BATCH * 32) / 256;

    // ---- fork: y path on s1 ----
    cudaStreamWaitEvent(s1, ePre, 0);
    gemm3bf<false, false><<<g1024, blk, SMEM_REQ, s1>>>(xhi, xlo, whi + OFF_YW0, wlo + OFF_YW0, yb0,
        1024, 1024, nullptr, y1hi, y1lo, nullptr, nullptr, nullptr);
    gemm3bf<false, true><<<g1024, blk, SMEM_REQ, s1>>>(y1hi, y1lo, whi + OFF_YW1, wlo + OFF_YW1, yb1,
        1024, 1024, fy, nullptr, nullptr, nullptr, nullptr, nullptr);
    head2_kernel<<<headBlocks, 256, 0, s1>>>(fy, t, yhW, yhb, out, 7);
    cudaEventRecord(eJ1, s1);

    // ---- fork: d path on s2 ----
    cudaStreamWaitEvent(s2, ePre, 0);
    gemm3bf<false, false><<<g1024, blk, SMEM_REQ, s2>>>(xhi, xlo, whi + OFF_DW0, wlo + OFF_DW0, db0,
        1024, 1024, nullptr, d1hi, d1lo, nullptr, nullptr, nullptr);
    gemm3bf<false, true><<<g1024, blk, SMEM_REQ, s2>>>(d1hi, d1lo, whi + OFF_DW1, wlo + OFF_DW1, db1,
        1024, 1024, fd, nullptr, nullptr, nullptr, nullptr, nullptr);
    head2_kernel<<<headBlocks, 256, 0, s2>>>(fd, t, dhW, dhb, out, 9);
    cudaEventRecord(eJ2, s2);

    // ---- fork: z path on s3 ----
    cudaStreamWaitEvent(s3, ePre, 0);
    gemm3bf<true, false><<<g1024, blk, SMEM_REQ, s3>>>(xhi, xlo, whi + OFF_ZW0, wlo + OFF_ZW0, zb0,
        1024, 1024, nullptr, z1hi, z1lo, yv, dv, zw0);
    gemm3bf<false, false><<<g1024, blk, SMEM_REQ, s3>>>(z1hi, z1lo, whi + OFF_ZW1, wlo + OFF_ZW1, zb1,
        1024, 1024, nullptr, z2hi, z2lo, nullptr, nullptr, nullptr);

    // ---- t path + bucketing on stream 0 ----
    gemm3bf<false, false><<<g256, blk, SMEM_REQ>>>(xhi, xlo, whi + OFF_TW0, wlo + OFF_TW0, tb0,
        256, 1024, nullptr, t1hi, t1lo, nullptr, nullptr, nullptr);
    gemm3bf<false, true><<<g256, blk, SMEM_REQ>>>(t1hi, t1lo, whi + OFF_TW1, wlo + OFF_TW1, tb1,
        256, 256, ft, nullptr, nullptr, nullptr, nullptr, nullptr);
    k_init<<<1, 32>>>();
    k_hist<<<(BATCH + 255) / 256, 256>>>(t);
    k_off<<<1, 32>>>();
    k_scatter<<<(BATCH + 255) / 256, 256>>>(t);
    cudaEventRecord(eBkt, 0);
    thead_kernel<<<headBlocks, 256>>>(ft, tw2, tb2, out);

    // ---- z head on s3 (needs bucketing + z2) ----
    cudaStreamWaitEvent(s3, eBkt, 0);
    zheadmma<<<dim3(4, 64, 7), blk, SMEM_REQ, s3>>>(z2hi, z2lo,
        whi + OFF_ZHW, wlo + OFF_ZHW, zhb, out);
    cudaEventRecord(eJ3, s3);

    // ---- join on stream 0 ----
    cudaStreamWaitEvent(0, eJ1, 0);
    cudaStreamWaitEvent(0, eJ2, 0);
    cudaStreamWaitEvent(0, eJ3, 0);
}

// round 6
// speedup vs baseline: 3.6507x; 1.0706x over previous
#include <cuda_runtime.h>
#include <cuda.h>
#include <cuda_bf16.h>
#include <cstdint>
#include <math.h>

#define BATCH 16384
#define OUTC  523   // 7 + 4 + 512

// ========================= PTX helpers (baseline sm_90-level, no arch-suffix) =========================
__device__ __forceinline__ uint32_t smem_u32(const void* p) {
    uint32_t a;
    asm("{ .reg .u64 t; cvta.to.shared.u64 t, %1; cvt.u32.u64 %0, t; }" : "=r"(a) : "l"(p));
    return a;
}
__device__ __forceinline__ void ldmx4(uint32_t& r0, uint32_t& r1, uint32_t& r2, uint32_t& r3, uint32_t addr) {
    asm volatile("ldmatrix.sync.aligned.m8n8.x4.shared.b16 {%0,%1,%2,%3}, [%4];"
                 : "=r"(r0), "=r"(r1), "=r"(r2), "=r"(r3) : "r"(addr));
}
__device__ __forceinline__ void mma16816(float* c, const uint32_t* a, uint32_t b0, uint32_t b1) {
    asm volatile("mma.sync.aligned.m16n8k16.row.col.f32.bf16.bf16.f32 "
                 "{%0,%1,%2,%3}, {%4,%5,%6,%7}, {%8,%9}, {%0,%1,%2,%3};"
                 : "+f"(c[0]), "+f"(c[1]), "+f"(c[2]), "+f"(c[3])
                 : "r"(a[0]), "r"(a[1]), "r"(a[2]), "r"(a[3]), "r"(b0), "r"(b1));
}
__device__ __forceinline__ uint32_t swz(uint32_t off) { return off ^ ((off >> 3) & 0x70); }

__device__ __forceinline__ void tma2d(uint32_t dst, const CUtensorMap* map, int cx, int cy, uint32_t mbar) {
    asm volatile("cp.async.bulk.tensor.2d.shared::cta.global.tile.mbarrier::complete_tx::bytes "
                 "[%0], [%1, {%2, %3}], [%4];"
                 :: "r"(dst), "l"(map), "r"(cx), "r"(cy), "r"(mbar) : "memory");
}
#define MBARRIER_INIT(addr, cnt) \
    asm volatile("mbarrier.init.shared.b64 [%0], %1;" :: "r"((uint32_t)(addr)), "r"((uint32_t)(cnt)) : "memory")
#define MBARRIER_EXPECT_TX(addr, bytes) \
    asm volatile("mbarrier.arrive.expect_tx.shared.b64 _, [%0], %1;" \
        :: "r"((uint32_t)(addr)), "r"((uint32_t)(bytes)) : "memory")
#define MBARRIER_WAIT_PARITY(mbar_smem_addr, phase_parity) do { \
    uint32_t _mbar = (uint32_t)(mbar_smem_addr); \
    uint32_t _parity = (uint32_t)(phase_parity); \
    uint32_t _done; \
    asm volatile("{\n\t.reg .pred p;\n\t" \
        "mbarrier.try_wait.parity.acquire.cta.shared::cta.b64 p, [%1], %2;\n\t" \
        "selp.b32 %0, 1, 0, p;\n\t}" : "=r"(_done) : "r"(_mbar), "r"(_parity) : "memory"); \
    if (!_done) { \
        asm volatile("{\n\t.reg .pred P1;\n\t" \
            "WAIT_LOOP_%=:\n\t" \
            "mbarrier.try_wait.parity.acquire.cta.shared::cta.b64 P1, [%0], %1, 0x989680;\n\t" \
            "@P1 bra.uni WAIT_DONE_%=;\n\t" \
            "bra.uni WAIT_LOOP_%=;\n\t" \
            "WAIT_DONE_%=:\n\t}" :: "r"(_mbar), "r"(_parity) : "memory"); \
    } \
} while(0)

// ========================= scratch (per-path, concurrent-safe) =========================
__device__ __align__(1024) __nv_bfloat16 g_xhi[BATCH * 1024];
__device__ __align__(1024) __nv_bfloat16 g_xlo[BATCH * 1024];
__device__ __align__(1024) __nv_bfloat16 g_y1hi[BATCH * 1024];
__device__ __align__(1024) __nv_bfloat16 g_y1lo[BATCH * 1024];
__device__ __align__(1024) __nv_bfloat16 g_d1hi[BATCH * 1024];
__device__ __align__(1024) __nv_bfloat16 g_d1lo[BATCH * 1024];
__device__ __align__(1024) __nv_bfloat16 g_z1hi[BATCH * 1024];   // gathered (bucket order)
__device__ __align__(1024) __nv_bfloat16 g_z1lo[BATCH * 1024];
__device__ __align__(1024) __nv_bfloat16 g_z2hi[BATCH * 1024];   // gathered (bucket order)
__device__ __align__(1024) __nv_bfloat16 g_z2lo[BATCH * 1024];
__device__ __align__(1024) __nv_bfloat16 g_t1hi[BATCH * 256];
__device__ __align__(1024) __nv_bfloat16 g_t1lo[BATCH * 256];
__device__ float g_fy[BATCH * 1024];
__device__ float g_fd[BATCH * 1024];
__device__ float g_ft[BATCH * 256];
__device__ __align__(1024) __nv_bfloat16 g_whi[10300000];
__device__ __align__(1024) __nv_bfloat16 g_wlo[10300000];
__device__ int g_ridx[BATCH];
__device__ int g_pos[BATCH];
__device__ int g_cnt[8];
__device__ int g_off[8];
__device__ int g_cur[8];

// weight-pool offsets (elements)
#define OFF_TW0 0
#define OFF_TW1 262144
#define OFF_YW0 327680
#define OFF_YW1 1376256
#define OFF_DW0 2424832
#define OFF_DW1 3473408
#define OFF_ZW0 4521984
#define OFF_ZW1 5570560
#define OFF_ZHW 6619136   // + t*524288 ; contiguous [7*512, 1024]

__device__ __forceinline__ float elu_f(float v) { return v > 0.f ? v : expm1f(v); }
__device__ __forceinline__ float softplus_f(float v) {
    return fmaxf(v, 0.f) + log1pf(expf(-fabsf(v)));
}

// ========================= preprocessing =========================
__global__ void xsplit_kernel(const float* __restrict__ x, __nv_bfloat16* __restrict__ hi,
                              __nv_bfloat16* __restrict__ lo, int n) {
    int i = blockIdx.x * blockDim.x + threadIdx.x;
    if (i < n) {
        float v = x[i];
        __nv_bfloat16 h = __float2bfloat16(v);
        hi[i] = h;
        lo[i] = __float2bfloat16(v - __bfloat162float(h));
    }
}
struct WEnt { const float* p; unsigned long long off; int kd, n; };
struct WTab { WEnt e[15]; };
__global__ void wsplit_all(WTab tab, __nv_bfloat16* __restrict__ hi, __nv_bfloat16* __restrict__ lo) {
    WEnt E = tab.e[blockIdx.z];
    int n0 = blockIdx.x * 32, k0 = blockIdx.y * 32;
    if (n0 >= E.n || k0 >= E.kd) return;
    __shared__ float tile[32][33];
    int tx = threadIdx.x, ty = threadIdx.y;
    for (int i = ty; i < 32; i += 8)
        tile[i][tx] = E.p[(size_t)(k0 + i) * E.n + n0 + tx];
    __syncthreads();
    __nv_bfloat16* H = hi + E.off;
    __nv_bfloat16* L = lo + E.off;
    for (int i = ty; i < 32; i += 8) {
        float v = tile[tx][i];
        size_t o = (size_t)(n0 + i) * E.kd + k0 + tx;
        __nv_bfloat16 h = __float2bfloat16(v);
        H[o] = h;
        L[o] = __float2bfloat16(v - __bfloat162float(h));
    }
}

// ========================= bucketing by t =========================
__global__ void k_init() { if (threadIdx.x < 8) g_cnt[threadIdx.x] = 0; }
__global__ void k_hist(const int* __restrict__ t) {
    int i = blockIdx.x * blockDim.x + threadIdx.x;
    if (i < BATCH) atomicAdd(&g_cnt[t[i]], 1);
}
__global__ void k_off() {
    if (threadIdx.x == 0) {
        int s = 0;
        for (int i = 0; i < 7; i++) { g_off[i] = s; g_cur[i] = s; s += g_cnt[i]; }
    }
}
__global__ void k_scatter(const int* __restrict__ t) {
    int i = blockIdx.x * blockDim.x + threadIdx.x;
    if (i < BATCH) {
        int p = atomicAdd(&g_cur[t[i]], 1);
        g_ridx[p] = i;
        g_pos[i] = p;
    }
}

// ========================= TMA-fed 3xBF16 mma.sync GEMM =========================
// CTA tile 256x128, K-chunk 64, 512 threads = 16 warps, warp tile 64x32, 2 TMA stages.
#define S_AH 0
#define S_AL 32768
#define S_BH 65536
#define S_BL 81920
#define STAGE_SZ 98304
#define CHUNK_BYTES 98304u
#define SMEM_REQ 198688   // 1024 pad + 2*98304 + mbarriers

__device__ __forceinline__ void compute_chunk(uint32_t st, int warp_m, int warp_n, int lane,
                                              float acc[4][4][4])
{
    const int lrow = lane & 7;
    const int lmat = lane >> 3;
#pragma unroll
    for (int ks = 0; ks < 4; ks++) {
        uint32_t bh[8], bl[8];
#pragma unroll
        for (int p = 0; p < 2; p++) {
            int ntile = p * 2 + (lmat >> 1);
            int half = lmat & 1;
            uint32_t off = (uint32_t)((warp_n * 32 + ntile * 8 + lrow) * 128 + (ks * 16 + half * 8) * 2);
            uint32_t a = swz(off);
            ldmx4(bh[p * 4 + 0], bh[p * 4 + 1], bh[p * 4 + 2], bh[p * 4 + 3], st + S_BH + a);
            ldmx4(bl[p * 4 + 0], bl[p * 4 + 1], bl[p * 4 + 2], bl[p * 4 + 3], st + S_BL + a);
        }
#pragma unroll
        for (int mt = 0; mt < 4; mt++) {
            uint32_t ah[4], al[4];
            uint32_t off = (uint32_t)((warp_m * 64 + mt * 16 + (lmat & 1) * 8 + lrow) * 128
                                      + (ks * 16 + (lmat >> 1) * 8) * 2);
            uint32_t a = swz(off);
            ldmx4(ah[0], ah[1], ah[2], ah[3], st + S_AH + a);
            ldmx4(al[0], al[1], al[2], al[3], st + S_AL + a);
#pragma unroll
            for (int nt = 0; nt < 4; nt++) {
                mma16816(acc[mt][nt], ah, bh[nt * 2], bh[nt * 2 + 1]);
                mma16816(acc[mt][nt], ah, bl[nt * 2], bl[nt * 2 + 1]);
                mma16816(acc[mt][nt], al, bh[nt * 2], bh[nt * 2 + 1]);
            }
        }
    }
}

template<bool ADD_YD, bool OUT_F32>
__global__ void __launch_bounds__(512, 1)
gemmT(const __grid_constant__ CUtensorMap tAh, const __grid_constant__ CUtensorMap tAl,
      const __grid_constant__ CUtensorMap tBh, const __grid_constant__ CUtensorMap tBl,
      const float* __restrict__ bias, int N, int Kd,
      float* __restrict__ outF, __nv_bfloat16* __restrict__ outHi, __nv_bfloat16* __restrict__ outLo,
      const float* __restrict__ yv, const float* __restrict__ dv, const float* __restrict__ wyd,
      const int* __restrict__ rowmap)
{
    extern __shared__ char smraw[];
    uint32_t sb = smem_u32(smraw);
    uint32_t ab = (sb + 1023u) & ~1023u;
    const uint32_t mbar = ab + 2 * STAGE_SZ;

    const int tid = threadIdx.x;
    const int wid = tid >> 5;
    const int lane = tid & 31;
    const int warp_m = wid & 3;
    const int warp_n = wid >> 2;
    const int bm = blockIdx.y * 256, bn = blockIdx.x * 128;
    const int nc = Kd >> 6;

    if (tid == 0) { MBARRIER_INIT(mbar, 1); MBARRIER_INIT(mbar + 8, 1); }
    __syncthreads();
    if (tid == 0) {
        MBARRIER_EXPECT_TX(mbar, CHUNK_BYTES);
        tma2d(ab + S_AH, &tAh, 0, bm, mbar);
        tma2d(ab + S_AL, &tAl, 0, bm, mbar);
        tma2d(ab + S_BH, &tBh, 0, bn, mbar);
        tma2d(ab + S_BL, &tBl, 0, bn, mbar);
        MBARRIER_EXPECT_TX(mbar + 8, CHUNK_BYTES);
        tma2d(ab + STAGE_SZ + S_AH, &tAh, 64, bm, mbar + 8);
        tma2d(ab + STAGE_SZ + S_AL, &tAl, 64, bm, mbar + 8);
        tma2d(ab + STAGE_SZ + S_BH, &tBh, 64, bn, mbar + 8);
        tma2d(ab + STAGE_SZ + S_BL, &tBl, 64, bn, mbar + 8);
    }

    float acc[4][4][4];
#pragma unroll
    for (int i = 0; i < 4; i++)
#pragma unroll
        for (int j = 0; j < 4; j++)
#pragma unroll
            for (int q = 0; q < 4; q++) acc[i][j][q] = 0.f;

    int ph0 = 0, ph1 = 0;
    for (int ch = 0; ch < nc; ch++) {
        int s = ch & 1;
        if (s == 0) { MBARRIER_WAIT_PARITY(mbar, ph0); ph0 ^= 1; }
        else        { MBARRIER_WAIT_PARITY(mbar + 8, ph1); ph1 ^= 1; }
        compute_chunk(ab + s * STAGE_SZ, warp_m, warp_n, lane, acc);
        __syncthreads();
        if (tid == 0 && ch + 2 < nc) {
            uint32_t st = ab + s * STAGE_SZ;
            uint32_t mb = mbar + s * 8;
            int k0 = (ch + 2) * 64;
            MBARRIER_EXPECT_TX(mb, CHUNK_BYTES);
            tma2d(st + S_AH, &tAh, k0, bm, mb);
            tma2d(st + S_AL, &tAl, k0, bm, mb);
            tma2d(st + S_BH, &tBh, k0, bn, mb);
            tma2d(st + S_BL, &tBl, k0, bn, mb);
        }
    }

    // ---- epilogue ----
    const int tgm = lane >> 2;
    const int tgn = (lane & 3) * 2;
#pragma unroll
    for (int mt = 0; mt < 4; mt++) {
#pragma unroll
        for (int dh = 0; dh < 2; dh++) {
            int m = bm + warp_m * 64 + mt * 16 + tgm + dh * 8;
            float ya = 0.f, da = 0.f;
            if (ADD_YD) { ya = __ldg(yv + m); da = __ldg(dv + m); }
            int mo = rowmap ? rowmap[m] : m;
#pragma unroll
            for (int nt = 0; nt < 4; nt++) {
                int n = bn + warp_n * 32 + nt * 8 + tgn;
                float v0 = acc[mt][nt][dh * 2 + 0];
                float v1 = acc[mt][nt][dh * 2 + 1];
                float2 bb = *(const float2*)(bias + n);
                v0 += bb.x; v1 += bb.y;
                if (ADD_YD) {
                    float2 w0 = *(const float2*)(wyd + n);
                    float2 w1 = *(const float2*)(wyd + N + n);
                    v0 += ya * w0.x + da * w1.x;
                    v1 += ya * w0.y + da * w1.y;
                }
                v0 = elu_f(v0); v1 = elu_f(v1);
                if (OUT_F32) {
                    *(float2*)(outF + (size_t)m * N + n) = make_float2(v0, v1);
                } else {
                    __nv_bfloat16 h0 = __float2bfloat16(v0);
                    __nv_bfloat16 h1 = __float2bfloat16(v1);
                    __nv_bfloat162 hp; hp.x = h0; hp.y = h1;
                    __nv_bfloat162 lp;
                    lp.x = __float2bfloat16(v0 - __bfloat162float(h0));
                    lp.y = __float2bfloat16(v1 - __bfloat162float(h1));
                    *(__nv_bfloat162*)(outHi + (size_t)mo * N + n) = hp;
                    *(__nv_bfloat162*)(outLo + (size_t)mo * N + n) = lp;
                }
            }
        }
    }
}

// ========================= z head: grouped GEMM over gathered rows (TMA) =========================
__global__ void __launch_bounds__(512, 1)
zheadT(const __grid_constant__ CUtensorMap tAh, const __grid_constant__ CUtensorMap tAl,
       const __grid_constant__ CUtensorMap tBh, const __grid_constant__ CUtensorMap tBl,
       const float* __restrict__ zhb, float* __restrict__ out)
{
    const int grp = blockIdx.z;
    const int cnt = g_cnt[grp];
    const int m0 = blockIdx.y * 256;
    if (m0 >= cnt) return;
    const int base = g_off[grp];
    const int bn = blockIdx.x * 128;
    const int brow = grp * 512 + bn;   // row into the [3584,1024] zhW pool
    const int arow = base + m0;        // row into gathered hidden

    extern __shared__ char smraw[];
    uint32_t sb = smem_u32(smraw);
    uint32_t ab = (sb + 1023u) & ~1023u;
    const uint32_t mbar = ab + 2 * STAGE_SZ;

    const int tid = threadIdx.x;
    const int wid = tid >> 5;
    const int lane = tid & 31;
    const int warp_m = wid & 3;
    const int warp_n = wid >> 2;

    if (tid == 0) { MBARRIER_INIT(mbar, 1); MBARRIER_INIT(mbar + 8, 1); }
    __syncthreads();
    if (tid == 0) {
        MBARRIER_EXPECT_TX(mbar, CHUNK_BYTES);
        tma2d(ab + S_AH, &tAh, 0, arow, mbar);
        tma2d(ab + S_AL, &tAl, 0, arow, mbar);
        tma2d(ab + S_BH, &tBh, 0, brow, mbar);
        tma2d(ab + S_BL, &tBl, 0, brow, mbar);
        MBARRIER_EXPECT_TX(mbar + 8, CHUNK_BYTES);
        tma2d(ab + STAGE_SZ + S_AH, &tAh, 64, arow, mbar + 8);
        tma2d(ab + STAGE_SZ + S_AL, &tAl, 64, arow, mbar + 8);
        tma2d(ab + STAGE_SZ + S_BH, &tBh, 64, brow, mbar + 8);
        tma2d(ab + STAGE_SZ + S_BL, &tBl, 64, brow, mbar + 8);
    }

    float acc[4][4][4];
#pragma unroll
    for (int i = 0; i < 4; i++)
#pragma unroll
        for (int j = 0; j < 4; j++)
#pragma unroll
            for (int q = 0; q < 4; q++) acc[i][j][q] = 0.f;

    int ph0 = 0, ph1 = 0;
    for (int ch = 0; ch < 16; ch++) {
        int s = ch & 1;
        if (s == 0) { MBARRIER_WAIT_PARITY(mbar, ph0); ph0 ^= 1; }
        else        { MBARRIER_WAIT_PARITY(mbar + 8, ph1); ph1 ^= 1; }
        compute_chunk(ab + s * STAGE_SZ, warp_m, warp_n, lane, acc);
        __syncthreads();
        if (tid == 0 && ch + 2 < 16) {
            uint32_t st = ab + s * STAGE_SZ;
            uint32_t mb = mbar + s * 8;
            int k0 = (ch + 2) * 64;
            MBARRIER_EXPECT_TX(mb, CHUNK_BYTES);
            tma2d(st + S_AH, &tAh, k0, arow, mb);
            tma2d(st + S_AL, &tAl, k0, arow, mb);
            tma2d(st + S_BH, &tBh, k0, brow, mb);
            tma2d(st + S_BL, &tBl, k0, brow, mb);
        }
    }

    const int tgm = lane >> 2;
    const int tgn = (lane & 3) * 2;
#pragma unroll
    for (int mt = 0; mt < 4; mt++) {
#pragma unroll
        for (int dh = 0; dh < 2; dh++) {
            int mloc = warp_m * 64 + mt * 16 + tgm + dh * 8;
            int gi = m0 + mloc;
            if (gi >= cnt) continue;
            int rg = g_ridx[base + gi];
            float* op = out + (size_t)rg * OUTC + 11;
#pragma unroll
            for (int nt = 0; nt < 4; nt++) {
                int n = bn + warp_n * 32 + nt * 8 + tgn;
                float v0 = acc[mt][nt][dh * 2 + 0] + __ldg(zhb + grp * 512 + n);
                float v1 = acc[mt][nt][dh * 2 + 1] + __ldg(zhb + grp * 512 + n + 1);
                if (n < 256) {
                    v0 = fminf(fmaxf(v0, -100.f), 100.f);
                    v1 = fminf(fmaxf(v1, -100.f), 100.f);
                } else {
                    v0 = fminf(softplus_f(v0) + 0.001f, 100.f);
                    v1 = fminf(softplus_f(v1) + 0.001f, 100.f);
                }
                op[n] = v0;
                op[n + 1] = v1;
            }
        }
    }
}

// ========================= small head kernels (fp32) =========================
__global__ void thead_kernel(const float* __restrict__ hid, const float* __restrict__ tw2,
                             const float* __restrict__ tb2, float* __restrict__ out)
{
    int w = (blockIdx.x * blockDim.x + threadIdx.x) >> 5;
    int lane = threadIdx.x & 31;
    if (w >= BATCH) return;
    const float* hr = hid + (size_t)w * 256;
    float acc[7] = {0.f, 0.f, 0.f, 0.f, 0.f, 0.f, 0.f};
    for (int k = lane; k < 256; k += 32) {
        float h = hr[k];
        const float* wr = tw2 + k * 7;
#pragma unroll
        for (int j = 0; j < 7; j++) acc[j] = fmaf(h, wr[j], acc[j]);
    }
#pragma unroll
    for (int j = 0; j < 7; j++)
        for (int o = 16; o > 0; o >>= 1) acc[j] += __shfl_xor_sync(0xffffffffu, acc[j], o);
    if (lane == 0) {
#pragma unroll
        for (int j = 0; j < 7; j++) {
            float v = elu_f(acc[j] + tb2[j]);
            out[(size_t)w * OUTC + j] = fminf(fmaxf(v, -10.f), 10.f);
        }
    }
}
__global__ void head2_kernel(const float* __restrict__ hid, const int* __restrict__ t,
                             const float* __restrict__ hW, const float* __restrict__ hb,
                             float* __restrict__ out, int col0)
{
    int w = (blockIdx.x * blockDim.x + threadIdx.x) >> 5;
    int lane = threadIdx.x & 31;
    if (w >= BATCH) return;
    int tt = t[w];
    const float*  hr = hid + (size_t)w * 1024;
    const float2* wp = (const float2*)(hW + (size_t)tt * 2048);
    float a0 = 0.f, a1 = 0.f;
    for (int k = lane; k < 1024; k += 32) {
        float h = hr[k];
        float2 ww = wp[k];
        a0 = fmaf(h, ww.x, a0);
        a1 = fmaf(h, ww.y, a1);
    }
    for (int o = 16; o > 0; o >>= 1) {
        a0 += __shfl_xor_sync(0xffffffffu, a0, o);
        a1 += __shfl_xor_sync(0xffffffffu, a1, o);
    }
    if (lane == 0) {
        float loc = fminf(fmaxf(a0 + hb[tt * 2 + 0], -1e6f), 1e6f);
        float sc  = fminf(softplus_f(a1 + hb[tt * 2 + 1]) + 1e-3f, 1e6f);
        out[(size_t)w * OUTC + col0]     = loc;
        out[(size_t)w * OUTC + col0 + 1] = sc;
    }
}

// ========================= host-side tensormap builder =========================
typedef CUresult (*PFN_tmap)(CUtensorMap*, CUtensorMapDataType, cuuint32_t, void*,
                             const cuuint64_t*, const cuuint64_t*, const cuuint32_t*,
                             const cuuint32_t*, CUtensorMapInterleave, CUtensorMapSwizzle,
                             CUtensorMapL2promotion, CUtensorMapFloatOOBfill);
static PFN_tmap tmap_fn() {
    static PFN_tmap fn = nullptr;
    if (!fn) {
        cudaDriverEntryPointQueryResult qr;
        cudaGetDriverEntryPointByVersion("cuTensorMapEncodeTiled", (void**)&fn, 12000,
                                         cudaEnableDefault, &qr);
    }
    return fn;
}
static void make_map(CUtensorMap* m, const __nv_bfloat16* base, unsigned long long inner,
                     unsigned long long outer, unsigned box_in, unsigned box_out) {
    cuuint64_t dims[2] = { inner, outer };
    cuuint64_t strides[1] = { inner * 2 };
    cuuint32_t box[2] = { box_in, box_out };
    cuuint32_t es[2] = { 1, 1 };
    tmap_fn()(m, CU_TENSOR_MAP_DATA_TYPE_BFLOAT16, 2, (void*)base, dims, strides, box, es,
              CU_TENSOR_MAP_INTERLEAVE_NONE, CU_TENSOR_MAP_SWIZZLE_128B,
              CU_TENSOR_MAP_L2_PROMOTION_L2_128B, CU_TENSOR_MAP_FLOAT_OOB_FILL_NONE);
}

// ========================= launch =========================
extern "C" void kernel_launch(void* const* d_in, const int* in_sizes, int n_in,
                              void* d_out, int out_size)
{
    const float* x   = (const float*)d_in[0];
    const int*   t   = (const int*)  d_in[1];
    const float* yv  = (const float*)d_in[2];
    const float* dv  = (const float*)d_in[3];
    const float* tw0 = (const float*)d_in[4];
    const float* tb0 = (const float*)d_in[5];
    const float* tw1 = (const float*)d_in[6];
    const float* tb1 = (const float*)d_in[7];
    const float* tw2 = (const float*)d_in[8];
    const float* tb2 = (const float*)d_in[9];
    const float* yw0 = (const float*)d_in[10];
    const float* yb0 = (const float*)d_in[11];
    const float* yw1 = (const float*)d_in[12];
    const float* yb1 = (const float*)d_in[13];
    const float* yhW = (const float*)d_in[14];
    const float* yhb = (const float*)d_in[15];
    const float* dw0 = (const float*)d_in[16];
    const float* db0 = (const float*)d_in[17];
    const float* dw1 = (const float*)d_in[18];
    const float* db1 = (const float*)d_in[19];
    const float* dhW = (const float*)d_in[20];
    const float* dhb = (const float*)d_in[21];
    const float* zw0 = (const float*)d_in[22];
    const float* zb0 = (const float*)d_in[23];
    const float* zw1 = (const float*)d_in[24];
    const float* zb1 = (const float*)d_in[25];
    const float* zhW = (const float*)d_in[26];
    const float* zhb = (const float*)d_in[27];
    float* out = (float*)d_out;

    __nv_bfloat16 *xhi, *xlo, *y1hi, *y1lo, *d1hi, *d1lo, *z1hi, *z1lo, *z2hi, *z2lo, *t1hi, *t1lo, *whi, *wlo;
    float *fy, *fd, *ft;
    int *posmap;
    cudaGetSymbolAddress((void**)&xhi, g_xhi);
    cudaGetSymbolAddress((void**)&xlo, g_xlo);
    cudaGetSymbolAddress((void**)&y1hi, g_y1hi);
    cudaGetSymbolAddress((void**)&y1lo, g_y1lo);
    cudaGetSymbolAddress((void**)&d1hi, g_d1hi);
    cudaGetSymbolAddress((void**)&d1lo, g_d1lo);
    cudaGetSymbolAddress((void**)&z1hi, g_z1hi);
    cudaGetSymbolAddress((void**)&z1lo, g_z1lo);
    cudaGetSymbolAddress((void**)&z2hi, g_z2hi);
    cudaGetSymbolAddress((void**)&z2lo, g_z2lo);
    cudaGetSymbolAddress((void**)&t1hi, g_t1hi);
    cudaGetSymbolAddress((void**)&t1lo, g_t1lo);
    cudaGetSymbolAddress((void**)&whi, g_whi);
    cudaGetSymbolAddress((void**)&wlo, g_wlo);
    cudaGetSymbolAddress((void**)&fy, g_fy);
    cudaGetSymbolAddress((void**)&fd, g_fd);
    cudaGetSymbolAddress((void**)&ft, g_ft);
    cudaGetSymbolAddress((void**)&posmap, g_pos);

    static cudaStream_t s1, s2, s3;
    static cudaEvent_t ePre, eJ1, eJ2, eJ3;
    static bool init = false;
    if (!init) {
        cudaStreamCreateWithFlags(&s1, cudaStreamNonBlocking);
        cudaStreamCreateWithFlags(&s2, cudaStreamNonBlocking);
        cudaStreamCreateWithFlags(&s3, cudaStreamNonBlocking);
        cudaEventCreateWithFlags(&ePre, cudaEventDisableTiming);
        cudaEventCreateWithFlags(&eJ1, cudaEventDisableTiming);
        cudaEventCreateWithFlags(&eJ2, cudaEventDisableTiming);
        cudaEventCreateWithFlags(&eJ3, cudaEventDisableTiming);
        cudaFuncSetAttribute((const void*)gemmT<false, false>, cudaFuncAttributeMaxDynamicSharedMemorySize, SMEM_REQ);
        cudaFuncSetAttribute((const void*)gemmT<false, true>,  cudaFuncAttributeMaxDynamicSharedMemorySize, SMEM_REQ);
        cudaFuncSetAttribute((const void*)gemmT<true, false>,  cudaFuncAttributeMaxDynamicSharedMemorySize, SMEM_REQ);
        cudaFuncSetAttribute((const void*)zheadT,               cudaFuncAttributeMaxDynamicSharedMemorySize, SMEM_REQ);
        init = true;
    }

    // ---- tensormaps (host-side; snapshotted into graph nodes at capture) ----
    static CUtensorMap M[30];
    make_map(&M[0],  xhi,  1024, BATCH, 64, 256);
    make_map(&M[1],  xlo,  1024, BATCH, 64, 256);
    make_map(&M[2],  y1hi, 1024, BATCH, 64, 256);
    make_map(&M[3],  y1lo, 1024, BATCH, 64, 256);
    make_map(&M[4],  d1hi, 1024, BATCH, 64, 256);
    make_map(&M[5],  d1lo, 1024, BATCH, 64, 256);
    make_map(&M[6],  z1hi, 1024, BATCH, 64, 256);
    make_map(&M[7],  z1lo, 1024, BATCH, 64, 256);
    make_map(&M[8],  z2hi, 1024, BATCH, 64, 256);
    make_map(&M[9],  z2lo, 1024, BATCH, 64, 256);
    make_map(&M[10], t1hi, 256,  BATCH, 64, 256);
    make_map(&M[11], t1lo, 256,  BATCH, 64, 256);
    make_map(&M[12], whi + OFF_TW0, 1024, 256,  64, 128);
    make_map(&M[13], wlo + OFF_TW0, 1024, 256,  64, 128);
    make_map(&M[14], whi + OFF_TW1, 256,  256,  64, 128);
    make_map(&M[15], wlo + OFF_TW1, 256,  256,  64, 128);
    make_map(&M[16], whi + OFF_YW0, 1024, 1024, 64, 128);
    make_map(&M[17], wlo + OFF_YW0, 1024, 1024, 64, 128);
    make_map(&M[18], whi + OFF_YW1, 1024, 1024, 64, 128);
    make_map(&M[19], wlo + OFF_YW1, 1024, 1024, 64, 128);
    make_map(&M[20], whi + OFF_DW0, 1024, 1024, 64, 128);
    make_map(&M[21], wlo + OFF_DW0, 1024, 1024, 64, 128);
    make_map(&M[22], whi + OFF_DW1, 1024, 1024, 64, 128);
    make_map(&M[23], wlo + OFF_DW1, 1024, 1024, 64, 128);
    make_map(&M[24], whi + OFF_ZW0, 1024, 1024, 64, 128);
    make_map(&M[25], wlo + OFF_ZW0, 1024, 1024, 64, 128);
    make_map(&M[26], whi + OFF_ZW1, 1024, 1024, 64, 128);
    make_map(&M[27], wlo + OFF_ZW1, 1024, 1024, 64, 128);
    make_map(&M[28], whi + OFF_ZHW, 1024, 3584, 64, 128);
    make_map(&M[29], wlo + OFF_ZHW, 1024, 3584, 64, 128);

    // ---- bucketing (needed by z layer1 scatter) + preprocessing on stream 0 ----
    k_init<<<1, 32>>>();
    k_hist<<<(BATCH + 255) / 256, 256>>>(t);
    k_off<<<1, 32>>>();
    k_scatter<<<(BATCH + 255) / 256, 256>>>(t);
    xsplit_kernel<<<(BATCH * 1024 + 255) / 256, 256>>>(x, xhi, xlo, BATCH * 1024);
    WTab tab;
    tab.e[0]  = { tw0,            OFF_TW0, 1024, 256 };
    tab.e[1]  = { tw1,            OFF_TW1, 256,  256 };
    tab.e[2]  = { yw0,            OFF_YW0, 1024, 1024 };
    tab.e[3]  = { yw1,            OFF_YW1, 1024, 1024 };
    tab.e[4]  = { dw0,            OFF_DW0, 1024, 1024 };
    tab.e[5]  = { dw1,            OFF_DW1, 1024, 1024 };
    tab.e[6]  = { zw0 + 2 * 1024, OFF_ZW0, 1024, 1024 };
    tab.e[7]  = { zw1,            OFF_ZW1, 1024, 1024 };
    for (int g = 0; g < 7; g++)
        tab.e[8 + g] = { zhW + (size_t)g * 1024 * 512,
                         (unsigned long long)(OFF_ZHW + (size_t)g * 524288), 1024, 512 };
    wsplit_all<<<dim3(32, 32, 15), dim3(32, 8)>>>(tab, whi, wlo);
    cudaEventRecord(ePre, 0);

    const dim3 blk(512);
    const dim3 g1024(8, 64);
    const dim3 g256(2, 64);
    const int headBlocks = (BATCH * 32) / 256;

    // ---- fork: y path on s1 ----
    cudaStreamWaitEvent(s1, ePre, 0);
    gemmT<false, false><<<g1024, blk, SMEM_REQ, s1>>>(M[0], M[1], M[16], M[17], yb0,
        1024, 1024, nullptr, y1hi, y1lo, nullptr, nullptr, nullptr, nullptr);
    gemmT<false, true><<<g1024, blk, SMEM_REQ, s1>>>(M[2], M[3], M[18], M[19], yb1,
        1024, 1024, fy, nullptr, nullptr, nullptr, nullptr, nullptr, nullptr);
    head2_kernel<<<headBlocks, 256, 0, s1>>>(fy, t, yhW, yhb, out, 7);
    cudaEventRecord(eJ1, s1);

    // ---- fork: d path on s2 ----
    cudaStreamWaitEvent(s2, ePre, 0);
    gemmT<false, false><<<g1024, blk, SMEM_REQ, s2>>>(M[0], M[1], M[20], M[21], db0,
        1024, 1024, nullptr, d1hi, d1lo, nullptr, nullptr, nullptr, nullptr);
    gemmT<false, true><<<g1024, blk, SMEM_REQ, s2>>>(M[4], M[5], M[22], M[23], db1,
        1024, 1024, fd, nullptr, nullptr, nullptr, nullptr, nullptr, nullptr);
    head2_kernel<<<headBlocks, 256, 0, s2>>>(fd, t, dhW, dhb, out, 9);
    cudaEventRecord(eJ2, s2);

    // ---- fork: z path on s3 (layer1 scatters rows into bucket order via g_pos) ----
    cudaStreamWaitEvent(s3, ePre, 0);
    gemmT<true, false><<<g1024, blk, SMEM_REQ, s3>>>(M[0], M[1], M[24], M[25], zb0,
        1024, 1024, nullptr, z1hi, z1lo, yv, dv, zw0, posmap);
    gemmT<false, false><<<g1024, blk, SMEM_REQ, s3>>>(M[6], M[7], M[26], M[27], zb1,
        1024, 1024, nullptr, z2hi, z2lo, nullptr, nullptr, nullptr, nullptr);
    zheadT<<<dim3(4, 64, 7), blk, SMEM_REQ, s3>>>(M[8], M[9], M[28], M[29], zhb, out);
    cudaEventRecord(eJ3, s3);

    // ---- t path on stream 0 ----
    gemmT<false, false><<<g256, blk, SMEM_REQ>>>(M[0], M[1], M[12], M[13], tb0,
        256, 1024, nullptr, t1hi, t1lo, nullptr, nullptr, nullptr, nullptr);
    gemmT<false, true><<<g256, blk, SMEM_REQ>>>(M[10], M[11], M[14], M[15], tb1,
        256, 256, ft, nullptr, nullptr, nullptr, nullptr, nullptr, nullptr);
    thead_kernel<<<headBlocks, 256>>>(ft, tw2, tb2, out);

    // ---- join on stream 0 ----
    cudaStreamWaitEvent(0, eJ1, 0);
    cudaStreamWaitEvent(0, eJ2, 0);
    cudaStreamWaitEvent(0, eJ3, 0);
}